// round 2
// baseline (speedup 1.0000x reference)
#include <cuda_runtime.h>
#include <math.h>

#define En 8
#define Bn 16
#define Cn 128
#define Hn 64
#define Wn 64
#define HWn 4096
#define HCn 512
#define OHWn 1024

// ---------------- scratch (device globals; no allocation) ----------------
__device__ float g_y[(size_t)En * Bn * Cn * HWn];      // 268 MB expert conv raw
__device__ float g_comb[(size_t)Bn * Cn * HWn];        // 33.5 MB combined
__device__ float g_h1[(size_t)Bn * HCn * HWn];         // 134 MB pw1 raw
__device__ float g_h2[(size_t)Bn * HCn * HWn];         // 134 MB dw raw
__device__ float g_o[(size_t)Bn * Cn * OHWn];          // 8.4 MB pw2 raw
__device__ float g_estats[En * Bn * 8 * 2];
__device__ float g_eca[En * Bn * Cn];
__device__ float g_ecb[En * Bn * Cn];
__device__ float g_wts[16][En];
__device__ float g_s1[Bn * 8 * 2];
__device__ float g_c1a[Bn * HCn];
__device__ float g_c1b[Bn * HCn];
__device__ float g_s2[Bn * 8 * 2];
__device__ float g_c2a[Bn * HCn];
__device__ float g_c2b[Bn * HCn];
__device__ float g_s3[Bn * 8 * 2];
__device__ float g_c3a[Bn * Cn];
__device__ float g_c3b[Bn * Cn];

__device__ __forceinline__ float silu_f(float v) { return v / (1.f + __expf(-v)); }

// ---------------- K0: zero the stats accumulators ----------------
__global__ void k_zero() {
    int i = blockIdx.x * 256 + threadIdx.x;
    if (i < En * Bn * 8 * 2) g_estats[i] = 0.f;
    if (i < Bn * 8 * 2) { g_s1[i] = 0.f; g_s2[i] = 0.f; g_s3[i] = 0.f; }
}

// ---------------- K1: expert 3x3 conv + GN stats ----------------
// block: one (e,b), 64 output channels, 16x16 spatial tile. 256 threads.
// thread: 8 px (half row) x 8 co register tile.
__global__ __launch_bounds__(256, 2) void k_expert(const float* __restrict__ x,
                                                   const float* __restrict__ w_exp) {
    const int tile = blockIdx.x;            // 0..15
    const int cob = blockIdx.y * 64;        // 0 or 64
    const int e = blockIdx.z >> 4;
    const int b = blockIdx.z & 15;
    const int ty0 = (tile >> 2) * 16, tx0 = (tile & 3) * 16;

    __shared__ float xs[8][18][19];
    __shared__ float ws[8][9][64];
    __shared__ float sred[8];

    const int tid = threadIdx.x;
    const int pg = tid & 31;                // 32 pixel groups (8 px each)
    const int cg = tid >> 5;                // 8 channel groups (8 co each)
    const int r = pg >> 1;                  // out row 0..15
    const int c0 = (pg & 1) * 8;            // out col base 0 or 8
    const int co0 = cg * 8;

    float acc[8][8];
    #pragma unroll
    for (int j = 0; j < 8; j++)
        #pragma unroll
        for (int o = 0; o < 8; o++) acc[j][o] = 0.f;

    const float* xb = x + (size_t)b * Cn * HWn;
    const float* wb = w_exp + ((size_t)e * Cn + cob) * Cn * 9;

    for (int cc = 0; cc < 16; cc++) {       // 16 chunks of 8 input channels
        for (int idx = tid; idx < 8 * 18 * 18; idx += 256) {
            int ci = idx / 324, rem = idx % 324;
            int rr = rem / 18, cx = rem % 18;
            int gy = ty0 - 1 + rr, gx = tx0 - 1 + cx;
            float v = 0.f;
            if ((unsigned)gy < 64u && (unsigned)gx < 64u)
                v = xb[(size_t)(cc * 8 + ci) * HWn + gy * 64 + gx];
            xs[ci][rr][cx] = v;
        }
        for (int idx = tid; idx < 8 * 9 * 64; idx += 256) {
            int ci = idx / 576, rem = idx % 576;
            int tap = rem / 64, co = rem % 64;
            ws[ci][tap][co] = wb[((size_t)co * Cn + cc * 8 + ci) * 9 + tap];
        }
        __syncthreads();
        #pragma unroll 2
        for (int ci = 0; ci < 8; ci++) {
            #pragma unroll
            for (int kh = 0; kh < 3; kh++) {
                float xv[10];
                #pragma unroll
                for (int j = 0; j < 10; j++) xv[j] = xs[ci][r + kh][c0 + j];
                #pragma unroll
                for (int kw = 0; kw < 3; kw++) {
                    float4 wa = *(const float4*)&ws[ci][kh * 3 + kw][co0];
                    float4 wbv = *(const float4*)&ws[ci][kh * 3 + kw][co0 + 4];
                    float w8[8] = {wa.x, wa.y, wa.z, wa.w, wbv.x, wbv.y, wbv.z, wbv.w};
                    #pragma unroll
                    for (int j = 0; j < 8; j++) {
                        float xvv = xv[j + kw];
                        #pragma unroll
                        for (int o = 0; o < 8; o++)
                            acc[j][o] = fmaf(xvv, w8[o], acc[j][o]);
                    }
                }
            }
        }
        __syncthreads();
    }

    // write y + local GN stats
    float lsum = 0.f, lsq = 0.f;
    size_t ybase = (size_t)(e * Bn + b) * Cn * HWn;
    #pragma unroll
    for (int o = 0; o < 8; o++) {
        int co = cob + co0 + o;
        float* rowp = g_y + ybase + (size_t)co * HWn + (ty0 + r) * 64 + tx0 + c0;
        float4 v0 = make_float4(acc[0][o], acc[1][o], acc[2][o], acc[3][o]);
        float4 v1 = make_float4(acc[4][o], acc[5][o], acc[6][o], acc[7][o]);
        lsum += v0.x + v0.y + v0.z + v0.w + v1.x + v1.y + v1.z + v1.w;
        lsq += v0.x * v0.x + v0.y * v0.y + v0.z * v0.z + v0.w * v0.w +
               v1.x * v1.x + v1.y * v1.y + v1.z * v1.z + v1.w * v1.w;
        *(float4*)rowp = v0;
        *(float4*)(rowp + 4) = v1;
    }
    if (tid < 8) sred[tid] = 0.f;
    __syncthreads();
    atomicAdd(&sred[(cg >> 1) * 2], lsum);
    atomicAdd(&sred[(cg >> 1) * 2 + 1], lsq);
    __syncthreads();
    if (tid < 4) {
        int g = (cob >> 4) + tid;
        atomicAdd(&g_estats[((e * Bn + b) * 8 + g) * 2], sred[tid * 2]);
        atomicAdd(&g_estats[((e * Bn + b) * 8 + g) * 2 + 1], sred[tid * 2 + 1]);
    }
}

// ---------------- K2: finalize expert GN coefs + router softmax ----------------
__global__ void k_router_fin(const float* __restrict__ gns, const float* __restrict__ gnb,
                             const float* __restrict__ w1, const float* __restrict__ b1,
                             const float* __restrict__ w2, const float* __restrict__ b2) {
    int tid = threadIdx.x;
    for (int i = tid; i < En * Bn * Cn; i += 256) {
        int e = i >> 11, b = (i >> 7) & 15, c = i & 127, g = c >> 4;
        float s = g_estats[((e * Bn + b) * 8 + g) * 2];
        float sq = g_estats[((e * Bn + b) * 8 + g) * 2 + 1];
        float mean = s * (1.f / 65536.f);
        float var = sq * (1.f / 65536.f) - mean * mean;
        float rstd = rsqrtf(var + 1e-5f);
        float a = rstd * gns[e * Cn + c];
        g_eca[i] = a;
        g_ecb[i] = gnb[e * Cn + c] - mean * a;
    }
    if (tid < 16) {
        int py = tid >> 2, px = tid & 3;
        float fe[32];
        float cy = (py + 0.5f) * 0.25f, cx = (px + 0.5f) * 0.25f;
        #pragma unroll
        for (int k = 0; k < 8; k++) {
            float fr = (float)(1 << k) * 3.14159265358979323846f;
            fe[k] = sinf(cy * fr);
            fe[8 + k] = cosf(cy * fr);
            fe[16 + k] = sinf(cx * fr);
            fe[24 + k] = cosf(cx * fr);
        }
        float hb[64];
        for (int j = 0; j < 64; j++) {
            float s = b1[j];
            for (int k = 0; k < 32; k++) s = fmaf(fe[k], w1[k * 64 + j], s);
            hb[j] = s / (1.f + expf(-s));
        }
        float lo[8];
        float mx = -1e30f;
        for (int ee = 0; ee < 8; ee++) {
            float s = b2[ee];
            for (int j = 0; j < 64; j++) s = fmaf(hb[j], w2[j * 8 + ee], s);
            lo[ee] = s;
            mx = fmaxf(mx, s);
        }
        float den = 0.f;
        for (int ee = 0; ee < 8; ee++) { lo[ee] = expf(lo[ee] - mx); den += lo[ee]; }
        float inv = 1.f / den;
        for (int ee = 0; ee < 8; ee++) g_wts[tid][ee] = lo[ee] * inv;
    }
}

// ---------------- K3: combine experts (normalize+silu+weighted sum+residual) ----------------
__global__ void k_combine(const float* __restrict__ x) {
    size_t t = (size_t)blockIdx.x * 256 + threadIdx.x;
    size_t i = t * 4;                        // element index, float4
    int b = (int)(i >> 19);
    int c = (int)(i >> 12) & 127;
    int p = (int)(i & 4095);
    int patch = ((p >> 6) >> 4) * 4 + ((p & 63) >> 4);
    float4 outv = *(const float4*)(x + i);
    #pragma unroll
    for (int e = 0; e < 8; e++) {
        int ebc = (e * Bn + b) * Cn + c;
        float a = g_eca[ebc], bb = g_ecb[ebc];
        float wt = g_wts[patch][e];
        float4 y = *(const float4*)(g_y + (size_t)ebc * HWn + p);
        outv.x += wt * silu_f(fmaf(y.x, a, bb));
        outv.y += wt * silu_f(fmaf(y.y, a, bb));
        outv.z += wt * silu_f(fmaf(y.z, a, bb));
        outv.w += wt * silu_f(fmaf(y.w, a, bb));
    }
    *(float4*)(g_comb + i) = outv;
}

// ---------------- K4: pw1 1x1 conv (128->512) + gn1 stats ----------------
// block: 64 hc x 256 px for one b; thread 8px x 8hc.
__global__ __launch_bounds__(256) void k_pw1(const float* __restrict__ w_pw1) {
    int pxb = blockIdx.x * 256;
    int hcb = blockIdx.y * 64;
    int b = blockIdx.z;
    __shared__ float As[16][64];
    __shared__ float Bs[16][256];
    __shared__ float sred[2];
    int tid = threadIdx.x;
    int pgg = tid & 31, cgg = tid >> 5;
    float acc[8][8];
    #pragma unroll
    for (int j = 0; j < 8; j++)
        #pragma unroll
        for (int o = 0; o < 8; o++) acc[j][o] = 0.f;

    for (int kb = 0; kb < 128; kb += 16) {
        for (int idx = tid; idx < 1024; idx += 256) {
            int hc = idx >> 4, kk = idx & 15;
            As[kk][hc] = w_pw1[(size_t)(hcb + hc) * 128 + kb + kk];
        }
        for (int idx = tid; idx < 4096; idx += 256) {
            int kk = idx >> 8, ii = idx & 255;
            Bs[kk][ii] = g_comb[(size_t)(b * Cn + kb + kk) * HWn + pxb + ii];
        }
        __syncthreads();
        #pragma unroll
        for (int kk = 0; kk < 16; kk++) {
            float4 xa = *(const float4*)&Bs[kk][pgg * 8];
            float4 xb2 = *(const float4*)&Bs[kk][pgg * 8 + 4];
            float xv[8] = {xa.x, xa.y, xa.z, xa.w, xb2.x, xb2.y, xb2.z, xb2.w};
            float4 wa = *(const float4*)&As[kk][cgg * 8];
            float4 wb2 = *(const float4*)&As[kk][cgg * 8 + 4];
            float wv[8] = {wa.x, wa.y, wa.z, wa.w, wb2.x, wb2.y, wb2.z, wb2.w};
            #pragma unroll
            for (int j = 0; j < 8; j++)
                #pragma unroll
                for (int o = 0; o < 8; o++)
                    acc[j][o] = fmaf(xv[j], wv[o], acc[j][o]);
        }
        __syncthreads();
    }
    float lsum = 0.f, lsq = 0.f;
    #pragma unroll
    for (int o = 0; o < 8; o++) {
        int hc = hcb + cgg * 8 + o;
        float* pp = g_h1 + (size_t)(b * HCn + hc) * HWn + pxb + pgg * 8;
        float4 v0 = make_float4(acc[0][o], acc[1][o], acc[2][o], acc[3][o]);
        float4 v1 = make_float4(acc[4][o], acc[5][o], acc[6][o], acc[7][o]);
        lsum += v0.x + v0.y + v0.z + v0.w + v1.x + v1.y + v1.z + v1.w;
        lsq += v0.x * v0.x + v0.y * v0.y + v0.z * v0.z + v0.w * v0.w +
               v1.x * v1.x + v1.y * v1.y + v1.z * v1.z + v1.w * v1.w;
        *(float4*)pp = v0;
        *(float4*)(pp + 4) = v1;
    }
    if (tid < 2) sred[tid] = 0.f;
    __syncthreads();
    atomicAdd(&sred[0], lsum);
    atomicAdd(&sred[1], lsq);
    __syncthreads();
    if (tid == 0) {
        int g = hcb >> 6;
        atomicAdd(&g_s1[(b * 8 + g) * 2], sred[0]);
        atomicAdd(&g_s1[(b * 8 + g) * 2 + 1], sred[1]);
    }
}

// ---------------- finalize kernels ----------------
__global__ void k_fin1(const float* __restrict__ s, const float* __restrict__ bias) {
    int i = blockIdx.x * 256 + threadIdx.x;
    if (i >= Bn * HCn) return;
    int b = i / HCn, c = i % HCn, g = c >> 6;
    float su = g_s1[(b * 8 + g) * 2], sq = g_s1[(b * 8 + g) * 2 + 1];
    float mean = su * (1.f / 262144.f);
    float var = sq * (1.f / 262144.f) - mean * mean;
    float rstd = rsqrtf(var + 1e-5f);
    float a = rstd * s[c];
    g_c1a[i] = a;
    g_c1b[i] = bias[c] - mean * a;
}
__global__ void k_fin2(const float* __restrict__ s, const float* __restrict__ bias) {
    int i = blockIdx.x * 256 + threadIdx.x;
    if (i >= Bn * HCn) return;
    int b = i / HCn, c = i % HCn, g = c >> 6;
    float su = g_s2[(b * 8 + g) * 2], sq = g_s2[(b * 8 + g) * 2 + 1];
    float mean = su * (1.f / 262144.f);
    float var = sq * (1.f / 262144.f) - mean * mean;
    float rstd = rsqrtf(var + 1e-5f);
    float a = rstd * s[c];
    g_c2a[i] = a;
    g_c2b[i] = bias[c] - mean * a;
}
__global__ void k_fin3(const float* __restrict__ s, const float* __restrict__ bias) {
    int i = blockIdx.x * 256 + threadIdx.x;
    if (i >= Bn * Cn) return;
    int b = i / Cn, c = i % Cn, g = c >> 4;
    float su = g_s3[(b * 8 + g) * 2], sq = g_s3[(b * 8 + g) * 2 + 1];
    float mean = su * (1.f / 16384.f);
    float var = sq * (1.f / 16384.f) - mean * mean;
    float rstd = rsqrtf(var + 1e-5f);
    float a = rstd * s[c];
    g_c3a[i] = a;
    g_c3b[i] = bias[c] - mean * a;
}

// ---------------- K5: depthwise 3x3 on silu(gn1(h1)) + gn2 stats ----------------
__global__ __launch_bounds__(256) void k_dw(const float* __restrict__ w_dw) {
    int rt = blockIdx.x;     // 4 row tiles of 16
    int hc = blockIdx.y;     // 512
    int b = blockIdx.z;      // 16
    __shared__ float xs[18][66];
    __shared__ float sred[2];
    int tid = threadIdx.x;
    float a = g_c1a[b * HCn + hc], bb = g_c1b[b * HCn + hc];
    const float* src = g_h1 + (size_t)(b * HCn + hc) * HWn;
    int r0 = rt * 16;
    for (int idx = tid; idx < 18 * 66; idx += 256) {
        int rr = idx / 66, cx = idx % 66;
        int gy = r0 - 1 + rr, gx = cx - 1;
        float v = 0.f;
        if ((unsigned)gy < 64u && (unsigned)gx < 64u)
            v = silu_f(fmaf(src[gy * 64 + gx], a, bb));
        xs[rr][cx] = v;
    }
    float wd[9];
    #pragma unroll
    for (int t9 = 0; t9 < 9; t9++) wd[t9] = __ldg(&w_dw[hc * 9 + t9]);
    __syncthreads();
    float lsum = 0.f, lsq = 0.f;
    float* dst = g_h2 + (size_t)(b * HCn + hc) * HWn;
    #pragma unroll
    for (int k4 = 0; k4 < 4; k4++) {
        int idx = tid + k4 * 256;
        int row = idx >> 6, col = idx & 63;
        float sum = 0.f;
        #pragma unroll
        for (int kh = 0; kh < 3; kh++)
            #pragma unroll
            for (int kw = 0; kw < 3; kw++)
                sum = fmaf(wd[kh * 3 + kw], xs[row + kh][col + kw], sum);
        dst[(r0 + row) * 64 + col] = sum;
        lsum += sum;
        lsq += sum * sum;
    }
    if (tid < 2) sred[tid] = 0.f;
    __syncthreads();
    atomicAdd(&sred[0], lsum);
    atomicAdd(&sred[1], lsq);
    __syncthreads();
    if (tid == 0) {
        int g = hc >> 6;
        atomicAdd(&g_s2[(b * 8 + g) * 2], sred[0]);
        atomicAdd(&g_s2[(b * 8 + g) * 2 + 1], sred[1]);
    }
}

// ---------------- K6: pw2 1x1 stride-2 (512->128) + gn3 stats ----------------
// block: 64 co x 128 out px for one b; thread 8px x 4co.
__global__ __launch_bounds__(256) void k_pw2(const float* __restrict__ w_pw2) {
    int pxb = blockIdx.x * 128;  // 8 tiles over 1024 out px
    int cob = blockIdx.y * 64;   // 2 chunks
    int b = blockIdx.z;
    __shared__ float As[16][64];
    __shared__ float Bs[16][128];
    __shared__ float sred[8];
    int tid = threadIdx.x;
    int pg = tid & 15, cgp = tid >> 4;
    float acc[8][4];
    #pragma unroll
    for (int j = 0; j < 8; j++)
        #pragma unroll
        for (int o = 0; o < 4; o++) acc[j][o] = 0.f;

    for (int kb = 0; kb < 512; kb += 16) {
        for (int idx = tid; idx < 1024; idx += 256) {
            int co = idx >> 4, kk = idx & 15;
            As[kk][co] = w_pw2[(size_t)(cob + co) * 512 + kb + kk];
        }
        for (int idx = tid; idx < 2048; idx += 256) {
            int kk = idx >> 7, ii = idx & 127;
            int p = pxb + ii;
            int oh = p >> 5, ow = p & 31;
            int ch = kb + kk;
            float a = g_c2a[b * HCn + ch], bb = g_c2b[b * HCn + ch];
            float v = g_h2[(size_t)(b * HCn + ch) * HWn + oh * 128 + ow * 2];
            Bs[kk][ii] = silu_f(fmaf(v, a, bb));
        }
        __syncthreads();
        #pragma unroll
        for (int kk = 0; kk < 16; kk++) {
            float4 xa = *(const float4*)&Bs[kk][pg * 8];
            float4 xb2 = *(const float4*)&Bs[kk][pg * 8 + 4];
            float xv[8] = {xa.x, xa.y, xa.z, xa.w, xb2.x, xb2.y, xb2.z, xb2.w};
            float4 wa = *(const float4*)&As[kk][cgp * 4];
            float wv[4] = {wa.x, wa.y, wa.z, wa.w};
            #pragma unroll
            for (int j = 0; j < 8; j++)
                #pragma unroll
                for (int o = 0; o < 4; o++)
                    acc[j][o] = fmaf(xv[j], wv[o], acc[j][o]);
        }
        __syncthreads();
    }
    float lsum = 0.f, lsq = 0.f;
    #pragma unroll
    for (int o = 0; o < 4; o++) {
        int co = cob + cgp * 4 + o;
        float* dst = g_o + (size_t)(b * Cn + co) * OHWn + pxb + pg * 8;
        float4 v0 = make_float4(acc[0][o], acc[1][o], acc[2][o], acc[3][o]);
        float4 v1 = make_float4(acc[4][o], acc[5][o], acc[6][o], acc[7][o]);
        lsum += v0.x + v0.y + v0.z + v0.w + v1.x + v1.y + v1.z + v1.w;
        lsq += v0.x * v0.x + v0.y * v0.y + v0.z * v0.z + v0.w * v0.w +
               v1.x * v1.x + v1.y * v1.y + v1.z * v1.z + v1.w * v1.w;
        *(float4*)dst = v0;
        *(float4*)(dst + 4) = v1;
    }
    if (tid < 8) sred[tid] = 0.f;
    __syncthreads();
    atomicAdd(&sred[(cgp >> 2) * 2], lsum);
    atomicAdd(&sred[(cgp >> 2) * 2 + 1], lsq);
    __syncthreads();
    if (tid < 4) {
        int g = (cob >> 4) + tid;
        atomicAdd(&g_s3[(b * 8 + g) * 2], sred[tid * 2]);
        atomicAdd(&g_s3[(b * 8 + g) * 2 + 1], sred[tid * 2 + 1]);
    }
}

// ---------------- K7: final gn3 + silu ----------------
__global__ void k_out(float* __restrict__ out) {
    int i = blockIdx.x * 256 + threadIdx.x;   // 2,097,152 elements
    int b = i >> 17;
    int c = (i >> 10) & 127;
    out[i] = silu_f(fmaf(g_o[i], g_c3a[b * Cn + c], g_c3b[b * Cn + c]));
}

// ---------------- launch ----------------
extern "C" void kernel_launch(void* const* d_in, const int* in_sizes, int n_in,
                              void* d_out, int out_size) {
    const float* x      = (const float*)d_in[0];
    const float* w_exp  = (const float*)d_in[1];
    const float* gns    = (const float*)d_in[2];
    const float* gnb    = (const float*)d_in[3];
    const float* w1     = (const float*)d_in[4];
    const float* b1     = (const float*)d_in[5];
    const float* w2     = (const float*)d_in[6];
    const float* b2     = (const float*)d_in[7];
    const float* w_pw1  = (const float*)d_in[8];
    const float* gn1s   = (const float*)d_in[9];
    const float* gn1b   = (const float*)d_in[10];
    const float* w_dw   = (const float*)d_in[11];
    const float* gn2s   = (const float*)d_in[12];
    const float* gn2b   = (const float*)d_in[13];
    const float* w_pw2  = (const float*)d_in[14];
    const float* gn3s   = (const float*)d_in[15];
    const float* gn3b   = (const float*)d_in[16];
    float* out = (float*)d_out;

    k_zero<<<8, 256>>>();
    {
        dim3 g(16, 2, En * Bn);
        k_expert<<<g, 256>>>(x, w_exp);
    }
    k_router_fin<<<1, 256>>>(gns, gnb, w1, b1, w2, b2);
    k_combine<<<8192, 256>>>(x);
    {
        dim3 g(16, 8, Bn);
        k_pw1<<<g, 256>>>(w_pw1);
    }
    k_fin1<<<(Bn * HCn + 255) / 256, 256>>>(gn1s, gn1b);
    {
        dim3 g(4, HCn, Bn);
        k_dw<<<g, 256>>>(w_dw);
    }
    k_fin2<<<(Bn * HCn + 255) / 256, 256>>>(gn2s, gn2b);
    {
        dim3 g(8, 2, Bn);
        k_pw2<<<g, 256>>>(w_pw2);
    }
    k_fin3<<<(Bn * Cn + 255) / 256, 256>>>(gn3s, gn3b);
    k_out<<<8192, 256>>>(out);
}

// round 3
// speedup vs baseline: 1.0591x; 1.0591x over previous
#include <cuda_runtime.h>
#include <math.h>

#define En 8
#define Bn 16
#define Cn 128
#define Hn 64
#define Wn 64
#define HWn 4096
#define HCn 512
#define OHWn 1024

// ---------------- scratch (device globals; no allocation) ----------------
__device__ float g_y[(size_t)En * Bn * Cn * HWn];      // 268 MB expert conv raw
__device__ float g_comb[(size_t)Bn * Cn * HWn];        // 33.5 MB combined
__device__ float g_h1[(size_t)Bn * HCn * HWn];         // 134 MB pw1 raw
__device__ float g_h2[(size_t)Bn * HCn * HWn];         // 134 MB dw raw
__device__ float g_o[(size_t)Bn * Cn * OHWn];          // 8.4 MB pw2 raw
__device__ float g_estats[En * Bn * 8 * 2];
__device__ float g_eca[En * Bn * Cn];
__device__ float g_ecb[En * Bn * Cn];
__device__ float g_wts[16][En];
__device__ float g_s1[Bn * 8 * 2];
__device__ float g_c1a[Bn * HCn];
__device__ float g_c1b[Bn * HCn];
__device__ float g_s2[Bn * 8 * 2];
__device__ float g_c2a[Bn * HCn];
__device__ float g_c2b[Bn * HCn];
__device__ float g_s3[Bn * 8 * 2];
__device__ float g_c3a[Bn * Cn];
__device__ float g_c3b[Bn * Cn];

__device__ __forceinline__ float silu_f(float v) { return v / (1.f + __expf(-v)); }

// ---- packed f32x2 helpers (sm_100+: one instruction = two fp32 FMAs) ----
__device__ __forceinline__ unsigned long long pk2(float lo, float hi) {
    unsigned long long r;
    asm("mov.b64 %0, {%1, %2};" : "=l"(r) : "f"(lo), "f"(hi));
    return r;
}
__device__ __forceinline__ void ffma2(unsigned long long& d, unsigned long long a,
                                      unsigned long long b) {
    asm("fma.rn.f32x2 %0, %1, %2, %0;" : "+l"(d) : "l"(a), "l"(b));
}
__device__ __forceinline__ void unpk2(unsigned long long p, float& lo, float& hi) {
    asm("mov.b64 {%0, %1}, %2;" : "=f"(lo), "=f"(hi) : "l"(p));
}

// ---------------- K0: zero the stats accumulators ----------------
__global__ void k_zero() {
    int i = blockIdx.x * 256 + threadIdx.x;
    if (i < En * Bn * 8 * 2) g_estats[i] = 0.f;
    if (i < Bn * 8 * 2) { g_s1[i] = 0.f; g_s2[i] = 0.f; g_s3[i] = 0.f; }
}

// ---------------- K1: expert 3x3 conv + GN stats (f32x2 packed FMA) ----------------
// block: one (e,b), 64 output channels, 16x16 spatial tile. 256 threads.
// thread: 8 px (half row) x 8 co register tile; acc packed as 8px x 4 co-pairs.
__global__ __launch_bounds__(256, 2) void k_expert(const float* __restrict__ x,
                                                   const float* __restrict__ w_exp) {
    const int tile = blockIdx.x;            // 0..15
    const int cob = blockIdx.y * 64;        // 0 or 64
    const int e = blockIdx.z >> 4;
    const int b = blockIdx.z & 15;
    const int ty0 = (tile >> 2) * 16, tx0 = (tile & 3) * 16;

    __shared__ float xs[8][18][19];
    __shared__ float ws[8][9][64];
    __shared__ float sred[8];

    const int tid = threadIdx.x;
    const int pg = tid & 31;
    const int cg = tid >> 5;
    const int r = pg >> 1;
    const int c0 = (pg & 1) * 8;
    const int co0 = cg * 8;

    unsigned long long acc2[8][4];          // [px][co pair] — 64 fp32 accumulators
    const unsigned long long z2 = 0ull;
    #pragma unroll
    for (int j = 0; j < 8; j++)
        #pragma unroll
        for (int op = 0; op < 4; op++) acc2[j][op] = z2;

    const float* xb = x + (size_t)b * Cn * HWn;
    const float* wb = w_exp + ((size_t)e * Cn + cob) * Cn * 9;

    for (int cc = 0; cc < 16; cc++) {       // 16 chunks of 8 input channels
        for (int idx = tid; idx < 8 * 18 * 18; idx += 256) {
            int ci = idx / 324, rem = idx % 324;
            int rr = rem / 18, cx = rem % 18;
            int gy = ty0 - 1 + rr, gx = tx0 - 1 + cx;
            float v = 0.f;
            if ((unsigned)gy < 64u && (unsigned)gx < 64u)
                v = xb[(size_t)(cc * 8 + ci) * HWn + gy * 64 + gx];
            xs[ci][rr][cx] = v;
        }
        for (int idx = tid; idx < 8 * 9 * 64; idx += 256) {
            int ci = idx / 576, rem = idx % 576;
            int tap = rem / 64, co = rem % 64;
            ws[ci][tap][co] = wb[((size_t)co * Cn + cc * 8 + ci) * 9 + tap];
        }
        __syncthreads();
        #pragma unroll 2
        for (int ci = 0; ci < 8; ci++) {
            #pragma unroll
            for (int kh = 0; kh < 3; kh++) {
                unsigned long long xd[10];
                #pragma unroll
                for (int t = 0; t < 10; t++) {
                    float v = xs[ci][r + kh][c0 + t];
                    xd[t] = pk2(v, v);
                }
                #pragma unroll
                for (int kw = 0; kw < 3; kw++) {
                    const unsigned long long* wp =
                        (const unsigned long long*)&ws[ci][kh * 3 + kw][co0];
                    unsigned long long w0 = wp[0], w1 = wp[1], w2 = wp[2], w3 = wp[3];
                    #pragma unroll
                    for (int j = 0; j < 8; j++) {
                        unsigned long long xvv = xd[j + kw];
                        ffma2(acc2[j][0], xvv, w0);
                        ffma2(acc2[j][1], xvv, w1);
                        ffma2(acc2[j][2], xvv, w2);
                        ffma2(acc2[j][3], xvv, w3);
                    }
                }
            }
        }
        __syncthreads();
    }

    // write y + local GN stats
    float lsum = 0.f, lsq = 0.f;
    size_t ybase = (size_t)(e * Bn + b) * Cn * HWn;
    #pragma unroll
    for (int op = 0; op < 4; op++) {
        float vlo[8], vhi[8];
        #pragma unroll
        for (int j = 0; j < 8; j++) unpk2(acc2[j][op], vlo[j], vhi[j]);
        #pragma unroll
        for (int half = 0; half < 2; half++) {
            const float* v = half ? vhi : vlo;
            int co = cob + co0 + op * 2 + half;
            float* rowp = g_y + ybase + (size_t)co * HWn + (ty0 + r) * 64 + tx0 + c0;
            float4 v0 = make_float4(v[0], v[1], v[2], v[3]);
            float4 v1 = make_float4(v[4], v[5], v[6], v[7]);
            lsum += v0.x + v0.y + v0.z + v0.w + v1.x + v1.y + v1.z + v1.w;
            lsq += v0.x * v0.x + v0.y * v0.y + v0.z * v0.z + v0.w * v0.w +
                   v1.x * v1.x + v1.y * v1.y + v1.z * v1.z + v1.w * v1.w;
            *(float4*)rowp = v0;
            *(float4*)(rowp + 4) = v1;
        }
    }
    if (tid < 8) sred[tid] = 0.f;
    __syncthreads();
    atomicAdd(&sred[(cg >> 1) * 2], lsum);
    atomicAdd(&sred[(cg >> 1) * 2 + 1], lsq);
    __syncthreads();
    if (tid < 4) {
        int g = (cob >> 4) + tid;
        atomicAdd(&g_estats[((e * Bn + b) * 8 + g) * 2], sred[tid * 2]);
        atomicAdd(&g_estats[((e * Bn + b) * 8 + g) * 2 + 1], sred[tid * 2 + 1]);
    }
}

// ---------------- K2: finalize expert GN coefs + router softmax ----------------
__global__ void k_router_fin(const float* __restrict__ gns, const float* __restrict__ gnb,
                             const float* __restrict__ w1, const float* __restrict__ b1,
                             const float* __restrict__ w2, const float* __restrict__ b2) {
    int tid = threadIdx.x;
    for (int i = tid; i < En * Bn * Cn; i += 256) {
        int e = i >> 11, b = (i >> 7) & 15, c = i & 127, g = c >> 4;
        float s = g_estats[((e * Bn + b) * 8 + g) * 2];
        float sq = g_estats[((e * Bn + b) * 8 + g) * 2 + 1];
        float mean = s * (1.f / 65536.f);
        float var = sq * (1.f / 65536.f) - mean * mean;
        float rstd = rsqrtf(var + 1e-5f);
        float a = rstd * gns[e * Cn + c];
        g_eca[i] = a;
        g_ecb[i] = gnb[e * Cn + c] - mean * a;
    }
    if (tid < 16) {
        int py = tid >> 2, px = tid & 3;
        float fe[32];
        float cy = (py + 0.5f) * 0.25f, cx = (px + 0.5f) * 0.25f;
        #pragma unroll
        for (int k = 0; k < 8; k++) {
            float fr = (float)(1 << k) * 3.14159265358979323846f;
            fe[k] = sinf(cy * fr);
            fe[8 + k] = cosf(cy * fr);
            fe[16 + k] = sinf(cx * fr);
            fe[24 + k] = cosf(cx * fr);
        }
        float hb[64];
        for (int j = 0; j < 64; j++) {
            float s = b1[j];
            for (int k = 0; k < 32; k++) s = fmaf(fe[k], w1[k * 64 + j], s);
            hb[j] = s / (1.f + expf(-s));
        }
        float lo[8];
        float mx = -1e30f;
        for (int ee = 0; ee < 8; ee++) {
            float s = b2[ee];
            for (int j = 0; j < 64; j++) s = fmaf(hb[j], w2[j * 8 + ee], s);
            lo[ee] = s;
            mx = fmaxf(mx, s);
        }
        float den = 0.f;
        for (int ee = 0; ee < 8; ee++) { lo[ee] = expf(lo[ee] - mx); den += lo[ee]; }
        float inv = 1.f / den;
        for (int ee = 0; ee < 8; ee++) g_wts[tid][ee] = lo[ee] * inv;
    }
}

// ---------------- K3: combine experts ----------------
__global__ void k_combine(const float* __restrict__ x) {
    size_t t = (size_t)blockIdx.x * 256 + threadIdx.x;
    size_t i = t * 4;
    int b = (int)(i >> 19);
    int c = (int)(i >> 12) & 127;
    int p = (int)(i & 4095);
    int patch = ((p >> 6) >> 4) * 4 + ((p & 63) >> 4);
    float4 outv = *(const float4*)(x + i);
    #pragma unroll
    for (int e = 0; e < 8; e++) {
        int ebc = (e * Bn + b) * Cn + c;
        float a = g_eca[ebc], bb = g_ecb[ebc];
        float wt = g_wts[patch][e];
        float4 y = *(const float4*)(g_y + (size_t)ebc * HWn + p);
        outv.x += wt * silu_f(fmaf(y.x, a, bb));
        outv.y += wt * silu_f(fmaf(y.y, a, bb));
        outv.z += wt * silu_f(fmaf(y.z, a, bb));
        outv.w += wt * silu_f(fmaf(y.w, a, bb));
    }
    *(float4*)(g_comb + i) = outv;
}

// ---------------- K4: pw1 1x1 conv (128->512) + gn1 stats (f32x2) ----------------
__global__ __launch_bounds__(256) void k_pw1(const float* __restrict__ w_pw1) {
    int pxb = blockIdx.x * 256;
    int hcb = blockIdx.y * 64;
    int b = blockIdx.z;
    __shared__ float As[16][64];
    __shared__ float Bs[16][256];
    __shared__ float sred[2];
    int tid = threadIdx.x;
    int pgg = tid & 31, cgg = tid >> 5;
    unsigned long long acc2[8][4];
    #pragma unroll
    for (int j = 0; j < 8; j++)
        #pragma unroll
        for (int op = 0; op < 4; op++) acc2[j][op] = 0ull;

    for (int kb = 0; kb < 128; kb += 16) {
        for (int idx = tid; idx < 1024; idx += 256) {
            int hc = idx >> 4, kk = idx & 15;
            As[kk][hc] = w_pw1[(size_t)(hcb + hc) * 128 + kb + kk];
        }
        for (int idx = tid; idx < 4096; idx += 256) {
            int kk = idx >> 8, ii = idx & 255;
            Bs[kk][ii] = g_comb[(size_t)(b * Cn + kb + kk) * HWn + pxb + ii];
        }
        __syncthreads();
        #pragma unroll
        for (int kk = 0; kk < 16; kk++) {
            float4 xa = *(const float4*)&Bs[kk][pgg * 8];
            float4 xb2 = *(const float4*)&Bs[kk][pgg * 8 + 4];
            float xvf[8] = {xa.x, xa.y, xa.z, xa.w, xb2.x, xb2.y, xb2.z, xb2.w};
            const unsigned long long* wp = (const unsigned long long*)&As[kk][cgg * 8];
            unsigned long long w0 = wp[0], w1 = wp[1], w2 = wp[2], w3 = wp[3];
            #pragma unroll
            for (int j = 0; j < 8; j++) {
                unsigned long long xvv = pk2(xvf[j], xvf[j]);
                ffma2(acc2[j][0], xvv, w0);
                ffma2(acc2[j][1], xvv, w1);
                ffma2(acc2[j][2], xvv, w2);
                ffma2(acc2[j][3], xvv, w3);
            }
        }
        __syncthreads();
    }
    float lsum = 0.f, lsq = 0.f;
    #pragma unroll
    for (int op = 0; op < 4; op++) {
        float vlo[8], vhi[8];
        #pragma unroll
        for (int j = 0; j < 8; j++) unpk2(acc2[j][op], vlo[j], vhi[j]);
        #pragma unroll
        for (int half = 0; half < 2; half++) {
            const float* v = half ? vhi : vlo;
            int hc = hcb + cgg * 8 + op * 2 + half;
            float* pp = g_h1 + (size_t)(b * HCn + hc) * HWn + pxb + pgg * 8;
            float4 v0 = make_float4(v[0], v[1], v[2], v[3]);
            float4 v1 = make_float4(v[4], v[5], v[6], v[7]);
            lsum += v0.x + v0.y + v0.z + v0.w + v1.x + v1.y + v1.z + v1.w;
            lsq += v0.x * v0.x + v0.y * v0.y + v0.z * v0.z + v0.w * v0.w +
                   v1.x * v1.x + v1.y * v1.y + v1.z * v1.z + v1.w * v1.w;
            *(float4*)pp = v0;
            *(float4*)(pp + 4) = v1;
        }
    }
    if (tid < 2) sred[tid] = 0.f;
    __syncthreads();
    atomicAdd(&sred[0], lsum);
    atomicAdd(&sred[1], lsq);
    __syncthreads();
    if (tid == 0) {
        int g = hcb >> 6;
        atomicAdd(&g_s1[(b * 8 + g) * 2], sred[0]);
        atomicAdd(&g_s1[(b * 8 + g) * 2 + 1], sred[1]);
    }
}

// ---------------- finalize kernels ----------------
__global__ void k_fin1(const float* __restrict__ s, const float* __restrict__ bias) {
    int i = blockIdx.x * 256 + threadIdx.x;
    if (i >= Bn * HCn) return;
    int b = i / HCn, c = i % HCn, g = c >> 6;
    float su = g_s1[(b * 8 + g) * 2], sq = g_s1[(b * 8 + g) * 2 + 1];
    float mean = su * (1.f / 262144.f);
    float var = sq * (1.f / 262144.f) - mean * mean;
    float rstd = rsqrtf(var + 1e-5f);
    float a = rstd * s[c];
    g_c1a[i] = a;
    g_c1b[i] = bias[c] - mean * a;
}
__global__ void k_fin2(const float* __restrict__ s, const float* __restrict__ bias) {
    int i = blockIdx.x * 256 + threadIdx.x;
    if (i >= Bn * HCn) return;
    int b = i / HCn, c = i % HCn, g = c >> 6;
    float su = g_s2[(b * 8 + g) * 2], sq = g_s2[(b * 8 + g) * 2 + 1];
    float mean = su * (1.f / 262144.f);
    float var = sq * (1.f / 262144.f) - mean * mean;
    float rstd = rsqrtf(var + 1e-5f);
    float a = rstd * s[c];
    g_c2a[i] = a;
    g_c2b[i] = bias[c] - mean * a;
}
__global__ void k_fin3(const float* __restrict__ s, const float* __restrict__ bias) {
    int i = blockIdx.x * 256 + threadIdx.x;
    if (i >= Bn * Cn) return;
    int b = i / Cn, c = i % Cn, g = c >> 4;
    float su = g_s3[(b * 8 + g) * 2], sq = g_s3[(b * 8 + g) * 2 + 1];
    float mean = su * (1.f / 16384.f);
    float var = sq * (1.f / 16384.f) - mean * mean;
    float rstd = rsqrtf(var + 1e-5f);
    float a = rstd * s[c];
    g_c3a[i] = a;
    g_c3b[i] = bias[c] - mean * a;
}

// ---------------- K5: depthwise 3x3 on silu(gn1(h1)) + gn2 stats ----------------
__global__ __launch_bounds__(256) void k_dw(const float* __restrict__ w_dw) {
    int rt = blockIdx.x;
    int hc = blockIdx.y;
    int b = blockIdx.z;
    __shared__ float xs[18][66];
    __shared__ float sred[2];
    int tid = threadIdx.x;
    float a = g_c1a[b * HCn + hc], bb = g_c1b[b * HCn + hc];
    const float* src = g_h1 + (size_t)(b * HCn + hc) * HWn;
    int r0 = rt * 16;
    for (int idx = tid; idx < 18 * 66; idx += 256) {
        int rr = idx / 66, cx = idx % 66;
        int gy = r0 - 1 + rr, gx = cx - 1;
        float v = 0.f;
        if ((unsigned)gy < 64u && (unsigned)gx < 64u)
            v = silu_f(fmaf(src[gy * 64 + gx], a, bb));
        xs[rr][cx] = v;
    }
    float wd[9];
    #pragma unroll
    for (int t9 = 0; t9 < 9; t9++) wd[t9] = __ldg(&w_dw[hc * 9 + t9]);
    __syncthreads();
    float lsum = 0.f, lsq = 0.f;
    float* dst = g_h2 + (size_t)(b * HCn + hc) * HWn;
    #pragma unroll
    for (int k4 = 0; k4 < 4; k4++) {
        int idx = tid + k4 * 256;
        int row = idx >> 6, col = idx & 63;
        float sum = 0.f;
        #pragma unroll
        for (int kh = 0; kh < 3; kh++)
            #pragma unroll
            for (int kw = 0; kw < 3; kw++)
                sum = fmaf(wd[kh * 3 + kw], xs[row + kh][col + kw], sum);
        dst[(r0 + row) * 64 + col] = sum;
        lsum += sum;
        lsq += sum * sum;
    }
    if (tid < 2) sred[tid] = 0.f;
    __syncthreads();
    atomicAdd(&sred[0], lsum);
    atomicAdd(&sred[1], lsq);
    __syncthreads();
    if (tid == 0) {
        int g = hc >> 6;
        atomicAdd(&g_s2[(b * 8 + g) * 2], sred[0]);
        atomicAdd(&g_s2[(b * 8 + g) * 2 + 1], sred[1]);
    }
}

// ---------------- K6: pw2 1x1 stride-2 (512->128) + gn3 stats ----------------
__global__ __launch_bounds__(256) void k_pw2(const float* __restrict__ w_pw2) {
    int pxb = blockIdx.x * 128;
    int cob = blockIdx.y * 64;
    int b = blockIdx.z;
    __shared__ float As[16][64];
    __shared__ float Bs[16][128];
    __shared__ float sred[8];
    int tid = threadIdx.x;
    int pg = tid & 15, cgp = tid >> 4;
    float acc[8][4];
    #pragma unroll
    for (int j = 0; j < 8; j++)
        #pragma unroll
        for (int o = 0; o < 4; o++) acc[j][o] = 0.f;

    for (int kb = 0; kb < 512; kb += 16) {
        for (int idx = tid; idx < 1024; idx += 256) {
            int co = idx >> 4, kk = idx & 15;
            As[kk][co] = w_pw2[(size_t)(cob + co) * 512 + kb + kk];
        }
        for (int idx = tid; idx < 2048; idx += 256) {
            int kk = idx >> 7, ii = idx & 127;
            int p = pxb + ii;
            int oh = p >> 5, ow = p & 31;
            int ch = kb + kk;
            float a = g_c2a[b * HCn + ch], bb = g_c2b[b * HCn + ch];
            float v = g_h2[(size_t)(b * HCn + ch) * HWn + oh * 128 + ow * 2];
            Bs[kk][ii] = silu_f(fmaf(v, a, bb));
        }
        __syncthreads();
        #pragma unroll
        for (int kk = 0; kk < 16; kk++) {
            float4 xa = *(const float4*)&Bs[kk][pg * 8];
            float4 xb2 = *(const float4*)&Bs[kk][pg * 8 + 4];
            float xv[8] = {xa.x, xa.y, xa.z, xa.w, xb2.x, xb2.y, xb2.z, xb2.w};
            float4 wa = *(const float4*)&As[kk][cgp * 4];
            float wv[4] = {wa.x, wa.y, wa.z, wa.w};
            #pragma unroll
            for (int j = 0; j < 8; j++)
                #pragma unroll
                for (int o = 0; o < 4; o++)
                    acc[j][o] = fmaf(xv[j], wv[o], acc[j][o]);
        }
        __syncthreads();
    }
    float lsum = 0.f, lsq = 0.f;
    #pragma unroll
    for (int o = 0; o < 4; o++) {
        int co = cob + cgp * 4 + o;
        float* dst = g_o + (size_t)(b * Cn + co) * OHWn + pxb + pg * 8;
        float4 v0 = make_float4(acc[0][o], acc[1][o], acc[2][o], acc[3][o]);
        float4 v1 = make_float4(acc[4][o], acc[5][o], acc[6][o], acc[7][o]);
        lsum += v0.x + v0.y + v0.z + v0.w + v1.x + v1.y + v1.z + v1.w;
        lsq += v0.x * v0.x + v0.y * v0.y + v0.z * v0.z + v0.w * v0.w +
               v1.x * v1.x + v1.y * v1.y + v1.z * v1.z + v1.w * v1.w;
        *(float4*)dst = v0;
        *(float4*)(dst + 4) = v1;
    }
    if (tid < 8) sred[tid] = 0.f;
    __syncthreads();
    atomicAdd(&sred[(cgp >> 2) * 2], lsum);
    atomicAdd(&sred[(cgp >> 2) * 2 + 1], lsq);
    __syncthreads();
    if (tid < 4) {
        int g = (cob >> 4) + tid;
        atomicAdd(&g_s3[(b * 8 + g) * 2], sred[tid * 2]);
        atomicAdd(&g_s3[(b * 8 + g) * 2 + 1], sred[tid * 2 + 1]);
    }
}

// ---------------- K7: final gn3 + silu ----------------
__global__ void k_out(float* __restrict__ out) {
    int i = blockIdx.x * 256 + threadIdx.x;
    int b = i >> 17;
    int c = (i >> 10) & 127;
    out[i] = silu_f(fmaf(g_o[i], g_c3a[b * Cn + c], g_c3b[b * Cn + c]));
}

// ---------------- launch ----------------
extern "C" void kernel_launch(void* const* d_in, const int* in_sizes, int n_in,
                              void* d_out, int out_size) {
    const float* x      = (const float*)d_in[0];
    const float* w_exp  = (const float*)d_in[1];
    const float* gns    = (const float*)d_in[2];
    const float* gnb    = (const float*)d_in[3];
    const float* w1     = (const float*)d_in[4];
    const float* b1     = (const float*)d_in[5];
    const float* w2     = (const float*)d_in[6];
    const float* b2     = (const float*)d_in[7];
    const float* w_pw1  = (const float*)d_in[8];
    const float* gn1s   = (const float*)d_in[9];
    const float* gn1b   = (const float*)d_in[10];
    const float* w_dw   = (const float*)d_in[11];
    const float* gn2s   = (const float*)d_in[12];
    const float* gn2b   = (const float*)d_in[13];
    const float* w_pw2  = (const float*)d_in[14];
    const float* gn3s   = (const float*)d_in[15];
    const float* gn3b   = (const float*)d_in[16];
    float* out = (float*)d_out;

    k_zero<<<8, 256>>>();
    {
        dim3 g(16, 2, En * Bn);
        k_expert<<<g, 256>>>(x, w_exp);
    }
    k_router_fin<<<1, 256>>>(gns, gnb, w1, b1, w2, b2);
    k_combine<<<8192, 256>>>(x);
    {
        dim3 g(16, 8, Bn);
        k_pw1<<<g, 256>>>(w_pw1);
    }
    k_fin1<<<(Bn * HCn + 255) / 256, 256>>>(gn1s, gn1b);
    {
        dim3 g(4, HCn, Bn);
        k_dw<<<g, 256>>>(w_dw);
    }
    k_fin2<<<(Bn * HCn + 255) / 256, 256>>>(gn2s, gn2b);
    {
        dim3 g(8, 2, Bn);
        k_pw2<<<g, 256>>>(w_pw2);
    }
    k_fin3<<<(Bn * Cn + 255) / 256, 256>>>(gn3s, gn3b);
    k_out<<<8192, 256>>>(out);
}

// round 4
// speedup vs baseline: 1.3693x; 1.2929x over previous
#include <cuda_runtime.h>
#include <math.h>

#define En 8
#define Bn 16
#define Cn 128
#define Hn 64
#define Wn 64
#define HWn 4096
#define HCn 512
#define OHWn 1024

// ---------------- scratch (device globals; no allocation) ----------------
__device__ float g_y[(size_t)En * Bn * Cn * HWn];      // 268 MB expert conv raw
__device__ float g_comb[(size_t)Bn * Cn * HWn];        // 33.5 MB combined
__device__ float g_h1[(size_t)Bn * HCn * HWn];         // 134 MB pw1 raw
__device__ float g_h2[(size_t)Bn * HCn * HWn];         // 134 MB dw raw
__device__ float g_o[(size_t)Bn * Cn * OHWn];          // 8.4 MB pw2 raw
__device__ float g_estats[En * Bn * 8 * 2];
__device__ float g_eca[En * Bn * Cn];
__device__ float g_ecb[En * Bn * Cn];
__device__ float g_wts[16][En];
__device__ float g_s1[Bn * 8 * 2];
__device__ float g_c1a[Bn * HCn];
__device__ float g_c1b[Bn * HCn];
__device__ float g_s2[Bn * 8 * 2];
__device__ float g_c2a[Bn * HCn];
__device__ float g_c2b[Bn * HCn];
__device__ float g_s3[Bn * 8 * 2];
__device__ float g_c3a[Bn * Cn];
__device__ float g_c3b[Bn * Cn];

__device__ __forceinline__ float silu_f(float v) { return v / (1.f + __expf(-v)); }

__device__ __forceinline__ unsigned to_tf32(float f) {
    unsigned r;
    asm("cvt.rna.tf32.f32 %0, %1;" : "=r"(r) : "f"(f));
    return r;
}

__device__ __forceinline__ void mma_tf32(float& c0, float& c1, float& c2, float& c3,
                                         unsigned a0, unsigned a1, unsigned a2, unsigned a3,
                                         unsigned b0, unsigned b1) {
    asm volatile(
        "mma.sync.aligned.m16n8k8.row.col.f32.tf32.tf32.f32 "
        "{%0,%1,%2,%3}, {%4,%5,%6,%7}, {%8,%9}, {%0,%1,%2,%3};"
        : "+f"(c0), "+f"(c1), "+f"(c2), "+f"(c3)
        : "r"(a0), "r"(a1), "r"(a2), "r"(a3), "r"(b0), "r"(b1));
}

// ---- packed f32x2 helpers ----
__device__ __forceinline__ unsigned long long pk2(float lo, float hi) {
    unsigned long long r;
    asm("mov.b64 %0, {%1, %2};" : "=l"(r) : "f"(lo), "f"(hi));
    return r;
}
__device__ __forceinline__ void ffma2(unsigned long long& d, unsigned long long a,
                                      unsigned long long b) {
    asm("fma.rn.f32x2 %0, %1, %2, %0;" : "+l"(d) : "l"(a), "l"(b));
}
__device__ __forceinline__ void unpk2(unsigned long long p, float& lo, float& hi) {
    asm("mov.b64 {%0, %1}, %2;" : "=f"(lo), "=f"(hi) : "l"(p));
}

// ---------------- K0: zero the stats accumulators ----------------
__global__ void k_zero() {
    int i = blockIdx.x * 256 + threadIdx.x;
    if (i < En * Bn * 8 * 2) g_estats[i] = 0.f;
    if (i < Bn * 8 * 2) { g_s1[i] = 0.f; g_s2[i] = 0.f; g_s3[i] = 0.f; }
}

// ---------------- K1: expert 3x3 conv via tf32 mma.sync + GN stats ----------------
// block: one (e,b), all 128 co, 2 image rows (128 px). 8 warps; warp = 16 co x 128 px.
__global__ __launch_bounds__(256, 1) void k_expert(const float* __restrict__ x,
                                                   const float* __restrict__ w_exp) {
    const int ty0 = blockIdx.x * 2;         // 32 tiles of 2 rows
    const int e = blockIdx.z >> 4;
    const int b = blockIdx.z & 15;

    // A: W per chunk, all 9 taps: [tap][ci][co padded 136] tf32
    __shared__ unsigned ws_s[9][8][136];    // 39168 B
    // B: X halo strip: [ci][4 rows][66 cols] tf32
    __shared__ unsigned xs_s[8][4][66];     // 8448 B

    const int tid = threadIdx.x;
    const int wm = tid >> 5;                // warp id = co group (16 co)
    const int lane = tid & 31;
    const int grp = lane >> 2;              // 0..7
    const int tig = lane & 3;               // 0..3

    float acc[16][4];
    #pragma unroll
    for (int f = 0; f < 16; f++)
        #pragma unroll
        for (int q = 0; q < 4; q++) acc[f][q] = 0.f;

    const float* xb = x + (size_t)b * Cn * HWn;
    const float* wb = w_exp + (size_t)e * Cn * Cn * 9;

    for (int cc = 0; cc < 16; cc++) {
        // stage W: 128 co x 8 ci x 9 taps = 9216
        for (int idx = tid; idx < 9216; idx += 256) {
            int co = idx / 72, r72 = idx % 72;
            int ci = r72 / 9, tap = r72 % 9;
            ws_s[tap][ci][co] = to_tf32(wb[(size_t)co * (Cn * 9) + cc * 72 + r72]);
        }
        // stage X halo: 8 ci x 4 rows x 66 cols = 2112
        for (int idx = tid; idx < 2112; idx += 256) {
            int ci = idx / 264, rem = idx % 264;
            int row = rem / 66, cx = rem % 66;
            int gy = ty0 - 1 + row, gx = cx - 1;
            float v = 0.f;
            if ((unsigned)gy < 64u && (unsigned)gx < 64u)
                v = xb[(size_t)(cc * 8 + ci) * HWn + gy * 64 + gx];
            xs_s[ci][row][cx] = to_tf32(v);
        }
        __syncthreads();

        #pragma unroll
        for (int tap = 0; tap < 9; tap++) {
            const int kh = tap / 3, kw = tap % 3;
            const int co_r = wm * 16 + grp;
            unsigned a0 = ws_s[tap][tig][co_r];
            unsigned a1 = ws_s[tap][tig][co_r + 8];
            unsigned a2 = ws_s[tap][tig + 4][co_r];
            unsigned a3 = ws_s[tap][tig + 4][co_r + 8];
            #pragma unroll
            for (int f = 0; f < 16; f++) {
                int n = f * 8 + grp;
                int rt = n >> 6, colw = n & 63;
                unsigned b0 = xs_s[tig][rt + kh][colw + kw];
                unsigned b1 = xs_s[tig + 4][rt + kh][colw + kw];
                mma_tf32(acc[f][0], acc[f][1], acc[f][2], acc[f][3],
                         a0, a1, a2, a3, b0, b1);
            }
        }
        __syncthreads();
    }

    // epilogue: write y (float2 per frag half) + per-warp GN group stats
    float lsum = 0.f, lsq = 0.f;
    size_t ybase = (size_t)(e * Bn + b) * Cn * HWn;
    const int co_lo = wm * 16 + grp;
    #pragma unroll
    for (int f = 0; f < 16; f++) {
        int n = f * 8 + 2 * tig;
        int rt = n >> 6, colw = n & 63;
        size_t poff = (size_t)(ty0 + rt) * 64 + colw;
        float2 v0 = make_float2(acc[f][0], acc[f][1]);
        float2 v1 = make_float2(acc[f][2], acc[f][3]);
        *(float2*)(g_y + ybase + (size_t)co_lo * HWn + poff) = v0;
        *(float2*)(g_y + ybase + (size_t)(co_lo + 8) * HWn + poff) = v1;
        lsum += v0.x + v0.y + v1.x + v1.y;
        lsq += v0.x * v0.x + v0.y * v0.y + v1.x * v1.x + v1.y * v1.y;
    }
    #pragma unroll
    for (int off = 16; off > 0; off >>= 1) {
        lsum += __shfl_xor_sync(0xFFFFFFFFu, lsum, off);
        lsq += __shfl_xor_sync(0xFFFFFFFFu, lsq, off);
    }
    if (lane == 0) {
        atomicAdd(&g_estats[((e * Bn + b) * 8 + wm) * 2], lsum);
        atomicAdd(&g_estats[((e * Bn + b) * 8 + wm) * 2 + 1], lsq);
    }
}

// ---------------- K2: finalize expert GN coefs + router softmax ----------------
__global__ void k_router_fin(const float* __restrict__ gns, const float* __restrict__ gnb,
                             const float* __restrict__ w1, const float* __restrict__ b1,
                             const float* __restrict__ w2, const float* __restrict__ b2) {
    int tid = threadIdx.x;
    for (int i = tid; i < En * Bn * Cn; i += 256) {
        int e = i >> 11, b = (i >> 7) & 15, c = i & 127, g = c >> 4;
        float s = g_estats[((e * Bn + b) * 8 + g) * 2];
        float sq = g_estats[((e * Bn + b) * 8 + g) * 2 + 1];
        float mean = s * (1.f / 65536.f);
        float var = sq * (1.f / 65536.f) - mean * mean;
        float rstd = rsqrtf(var + 1e-5f);
        float a = rstd * gns[e * Cn + c];
        g_eca[i] = a;
        g_ecb[i] = gnb[e * Cn + c] - mean * a;
    }
    if (tid < 16) {
        int py = tid >> 2, px = tid & 3;
        float fe[32];
        float cy = (py + 0.5f) * 0.25f, cx = (px + 0.5f) * 0.25f;
        #pragma unroll
        for (int k = 0; k < 8; k++) {
            float fr = (float)(1 << k) * 3.14159265358979323846f;
            fe[k] = sinf(cy * fr);
            fe[8 + k] = cosf(cy * fr);
            fe[16 + k] = sinf(cx * fr);
            fe[24 + k] = cosf(cx * fr);
        }
        float hb[64];
        for (int j = 0; j < 64; j++) {
            float s = b1[j];
            for (int k = 0; k < 32; k++) s = fmaf(fe[k], w1[k * 64 + j], s);
            hb[j] = s / (1.f + expf(-s));
        }
        float lo[8];
        float mx = -1e30f;
        for (int ee = 0; ee < 8; ee++) {
            float s = b2[ee];
            for (int j = 0; j < 64; j++) s = fmaf(hb[j], w2[j * 8 + ee], s);
            lo[ee] = s;
            mx = fmaxf(mx, s);
        }
        float den = 0.f;
        for (int ee = 0; ee < 8; ee++) { lo[ee] = expf(lo[ee] - mx); den += lo[ee]; }
        float inv = 1.f / den;
        for (int ee = 0; ee < 8; ee++) g_wts[tid][ee] = lo[ee] * inv;
    }
}

// ---------------- K3: combine experts ----------------
__global__ void k_combine(const float* __restrict__ x) {
    size_t t = (size_t)blockIdx.x * 256 + threadIdx.x;
    size_t i = t * 4;
    int b = (int)(i >> 19);
    int c = (int)(i >> 12) & 127;
    int p = (int)(i & 4095);
    int patch = ((p >> 6) >> 4) * 4 + ((p & 63) >> 4);
    float4 outv = *(const float4*)(x + i);
    #pragma unroll
    for (int e = 0; e < 8; e++) {
        int ebc = (e * Bn + b) * Cn + c;
        float a = g_eca[ebc], bb = g_ecb[ebc];
        float wt = g_wts[patch][e];
        float4 y = *(const float4*)(g_y + (size_t)ebc * HWn + p);
        outv.x += wt * silu_f(fmaf(y.x, a, bb));
        outv.y += wt * silu_f(fmaf(y.y, a, bb));
        outv.z += wt * silu_f(fmaf(y.z, a, bb));
        outv.w += wt * silu_f(fmaf(y.w, a, bb));
    }
    *(float4*)(g_comb + i) = outv;
}

// ---------------- K4: pw1 1x1 conv (128->512) + gn1 stats (f32x2) ----------------
__global__ __launch_bounds__(256) void k_pw1(const float* __restrict__ w_pw1) {
    int pxb = blockIdx.x * 256;
    int hcb = blockIdx.y * 64;
    int b = blockIdx.z;
    __shared__ float As[16][64];
    __shared__ float Bs[16][256];
    __shared__ float sred[2];
    int tid = threadIdx.x;
    int pgg = tid & 31, cgg = tid >> 5;
    unsigned long long acc2[8][4];
    #pragma unroll
    for (int j = 0; j < 8; j++)
        #pragma unroll
        for (int op = 0; op < 4; op++) acc2[j][op] = 0ull;

    for (int kb = 0; kb < 128; kb += 16) {
        for (int idx = tid; idx < 1024; idx += 256) {
            int hc = idx >> 4, kk = idx & 15;
            As[kk][hc] = w_pw1[(size_t)(hcb + hc) * 128 + kb + kk];
        }
        for (int idx = tid; idx < 4096; idx += 256) {
            int kk = idx >> 8, ii = idx & 255;
            Bs[kk][ii] = g_comb[(size_t)(b * Cn + kb + kk) * HWn + pxb + ii];
        }
        __syncthreads();
        #pragma unroll
        for (int kk = 0; kk < 16; kk++) {
            float4 xa = *(const float4*)&Bs[kk][pgg * 8];
            float4 xb2 = *(const float4*)&Bs[kk][pgg * 8 + 4];
            float xvf[8] = {xa.x, xa.y, xa.z, xa.w, xb2.x, xb2.y, xb2.z, xb2.w};
            const unsigned long long* wp = (const unsigned long long*)&As[kk][cgg * 8];
            unsigned long long w0 = wp[0], w1 = wp[1], w2 = wp[2], w3 = wp[3];
            #pragma unroll
            for (int j = 0; j < 8; j++) {
                unsigned long long xvv = pk2(xvf[j], xvf[j]);
                ffma2(acc2[j][0], xvv, w0);
                ffma2(acc2[j][1], xvv, w1);
                ffma2(acc2[j][2], xvv, w2);
                ffma2(acc2[j][3], xvv, w3);
            }
        }
        __syncthreads();
    }
    float lsum = 0.f, lsq = 0.f;
    #pragma unroll
    for (int op = 0; op < 4; op++) {
        float vlo[8], vhi[8];
        #pragma unroll
        for (int j = 0; j < 8; j++) unpk2(acc2[j][op], vlo[j], vhi[j]);
        #pragma unroll
        for (int half = 0; half < 2; half++) {
            const float* v = half ? vhi : vlo;
            int hc = hcb + cgg * 8 + op * 2 + half;
            float* pp = g_h1 + (size_t)(b * HCn + hc) * HWn + pxb + pgg * 8;
            float4 v0 = make_float4(v[0], v[1], v[2], v[3]);
            float4 v1 = make_float4(v[4], v[5], v[6], v[7]);
            lsum += v0.x + v0.y + v0.z + v0.w + v1.x + v1.y + v1.z + v1.w;
            lsq += v0.x * v0.x + v0.y * v0.y + v0.z * v0.z + v0.w * v0.w +
                   v1.x * v1.x + v1.y * v1.y + v1.z * v1.z + v1.w * v1.w;
            *(float4*)pp = v0;
            *(float4*)(pp + 4) = v1;
        }
    }
    if (tid < 2) sred[tid] = 0.f;
    __syncthreads();
    atomicAdd(&sred[0], lsum);
    atomicAdd(&sred[1], lsq);
    __syncthreads();
    if (tid == 0) {
        int g = hcb >> 6;
        atomicAdd(&g_s1[(b * 8 + g) * 2], sred[0]);
        atomicAdd(&g_s1[(b * 8 + g) * 2 + 1], sred[1]);
    }
}

// ---------------- finalize kernels ----------------
__global__ void k_fin1(const float* __restrict__ s, const float* __restrict__ bias) {
    int i = blockIdx.x * 256 + threadIdx.x;
    if (i >= Bn * HCn) return;
    int b = i / HCn, c = i % HCn, g = c >> 6;
    float su = g_s1[(b * 8 + g) * 2], sq = g_s1[(b * 8 + g) * 2 + 1];
    float mean = su * (1.f / 262144.f);
    float var = sq * (1.f / 262144.f) - mean * mean;
    float rstd = rsqrtf(var + 1e-5f);
    float a = rstd * s[c];
    g_c1a[i] = a;
    g_c1b[i] = bias[c] - mean * a;
}
__global__ void k_fin2(const float* __restrict__ s, const float* __restrict__ bias) {
    int i = blockIdx.x * 256 + threadIdx.x;
    if (i >= Bn * HCn) return;
    int b = i / HCn, c = i % HCn, g = c >> 6;
    float su = g_s2[(b * 8 + g) * 2], sq = g_s2[(b * 8 + g) * 2 + 1];
    float mean = su * (1.f / 262144.f);
    float var = sq * (1.f / 262144.f) - mean * mean;
    float rstd = rsqrtf(var + 1e-5f);
    float a = rstd * s[c];
    g_c2a[i] = a;
    g_c2b[i] = bias[c] - mean * a;
}
__global__ void k_fin3(const float* __restrict__ s, const float* __restrict__ bias) {
    int i = blockIdx.x * 256 + threadIdx.x;
    if (i >= Bn * Cn) return;
    int b = i / Cn, c = i % Cn, g = c >> 4;
    float su = g_s3[(b * 8 + g) * 2], sq = g_s3[(b * 8 + g) * 2 + 1];
    float mean = su * (1.f / 16384.f);
    float var = sq * (1.f / 16384.f) - mean * mean;
    float rstd = rsqrtf(var + 1e-5f);
    float a = rstd * s[c];
    g_c3a[i] = a;
    g_c3b[i] = bias[c] - mean * a;
}

// ---------------- K5: depthwise 3x3 on silu(gn1(h1)) + gn2 stats ----------------
__global__ __launch_bounds__(256) void k_dw(const float* __restrict__ w_dw) {
    int rt = blockIdx.x;
    int hc = blockIdx.y;
    int b = blockIdx.z;
    __shared__ float xs[18][66];
    __shared__ float sred[2];
    int tid = threadIdx.x;
    float a = g_c1a[b * HCn + hc], bb = g_c1b[b * HCn + hc];
    const float* src = g_h1 + (size_t)(b * HCn + hc) * HWn;
    int r0 = rt * 16;
    for (int idx = tid; idx < 18 * 66; idx += 256) {
        int rr = idx / 66, cx = idx % 66;
        int gy = r0 - 1 + rr, gx = cx - 1;
        float v = 0.f;
        if ((unsigned)gy < 64u && (unsigned)gx < 64u)
            v = silu_f(fmaf(src[gy * 64 + gx], a, bb));
        xs[rr][cx] = v;
    }
    float wd[9];
    #pragma unroll
    for (int t9 = 0; t9 < 9; t9++) wd[t9] = __ldg(&w_dw[hc * 9 + t9]);
    __syncthreads();
    float lsum = 0.f, lsq = 0.f;
    float* dst = g_h2 + (size_t)(b * HCn + hc) * HWn;
    #pragma unroll
    for (int k4 = 0; k4 < 4; k4++) {
        int idx = tid + k4 * 256;
        int row = idx >> 6, col = idx & 63;
        float sum = 0.f;
        #pragma unroll
        for (int kh = 0; kh < 3; kh++)
            #pragma unroll
            for (int kw = 0; kw < 3; kw++)
                sum = fmaf(wd[kh * 3 + kw], xs[row + kh][col + kw], sum);
        dst[(r0 + row) * 64 + col] = sum;
        lsum += sum;
        lsq += sum * sum;
    }
    if (tid < 2) sred[tid] = 0.f;
    __syncthreads();
    atomicAdd(&sred[0], lsum);
    atomicAdd(&sred[1], lsq);
    __syncthreads();
    if (tid == 0) {
        int g = hc >> 6;
        atomicAdd(&g_s2[(b * 8 + g) * 2], sred[0]);
        atomicAdd(&g_s2[(b * 8 + g) * 2 + 1], sred[1]);
    }
}

// ---------------- K6: pw2 1x1 stride-2 (512->128) + gn3 stats ----------------
__global__ __launch_bounds__(256) void k_pw2(const float* __restrict__ w_pw2) {
    int pxb = blockIdx.x * 128;
    int cob = blockIdx.y * 64;
    int b = blockIdx.z;
    __shared__ float As[16][64];
    __shared__ float Bs[16][128];
    __shared__ float sred[8];
    int tid = threadIdx.x;
    int pg = tid & 15, cgp = tid >> 4;
    float acc[8][4];
    #pragma unroll
    for (int j = 0; j < 8; j++)
        #pragma unroll
        for (int o = 0; o < 4; o++) acc[j][o] = 0.f;

    for (int kb = 0; kb < 512; kb += 16) {
        for (int idx = tid; idx < 1024; idx += 256) {
            int co = idx >> 4, kk = idx & 15;
            As[kk][co] = w_pw2[(size_t)(cob + co) * 512 + kb + kk];
        }
        for (int idx = tid; idx < 2048; idx += 256) {
            int kk = idx >> 7, ii = idx & 127;
            int p = pxb + ii;
            int oh = p >> 5, ow = p & 31;
            int ch = kb + kk;
            float a = g_c2a[b * HCn + ch], bb = g_c2b[b * HCn + ch];
            float v = g_h2[(size_t)(b * HCn + ch) * HWn + oh * 128 + ow * 2];
            Bs[kk][ii] = silu_f(fmaf(v, a, bb));
        }
        __syncthreads();
        #pragma unroll
        for (int kk = 0; kk < 16; kk++) {
            float4 xa = *(const float4*)&Bs[kk][pg * 8];
            float4 xb2 = *(const float4*)&Bs[kk][pg * 8 + 4];
            float xv[8] = {xa.x, xa.y, xa.z, xa.w, xb2.x, xb2.y, xb2.z, xb2.w};
            float4 wa = *(const float4*)&As[kk][cgp * 4];
            float wv[4] = {wa.x, wa.y, wa.z, wa.w};
            #pragma unroll
            for (int j = 0; j < 8; j++)
                #pragma unroll
                for (int o = 0; o < 4; o++)
                    acc[j][o] = fmaf(xv[j], wv[o], acc[j][o]);
        }
        __syncthreads();
    }
    float lsum = 0.f, lsq = 0.f;
    #pragma unroll
    for (int o = 0; o < 4; o++) {
        int co = cob + cgp * 4 + o;
        float* dst = g_o + (size_t)(b * Cn + co) * OHWn + pxb + pg * 8;
        float4 v0 = make_float4(acc[0][o], acc[1][o], acc[2][o], acc[3][o]);
        float4 v1 = make_float4(acc[4][o], acc[5][o], acc[6][o], acc[7][o]);
        lsum += v0.x + v0.y + v0.z + v0.w + v1.x + v1.y + v1.z + v1.w;
        lsq += v0.x * v0.x + v0.y * v0.y + v0.z * v0.z + v0.w * v0.w +
               v1.x * v1.x + v1.y * v1.y + v1.z * v1.z + v1.w * v1.w;
        *(float4*)dst = v0;
        *(float4*)(dst + 4) = v1;
    }
    if (tid < 8) sred[tid] = 0.f;
    __syncthreads();
    atomicAdd(&sred[(cgp >> 2) * 2], lsum);
    atomicAdd(&sred[(cgp >> 2) * 2 + 1], lsq);
    __syncthreads();
    if (tid < 4) {
        int g = (cob >> 4) + tid;
        atomicAdd(&g_s3[(b * 8 + g) * 2], sred[tid * 2]);
        atomicAdd(&g_s3[(b * 8 + g) * 2 + 1], sred[tid * 2 + 1]);
    }
}

// ---------------- K7: final gn3 + silu ----------------
__global__ void k_out(float* __restrict__ out) {
    int i = blockIdx.x * 256 + threadIdx.x;
    int b = i >> 17;
    int c = (i >> 10) & 127;
    out[i] = silu_f(fmaf(g_o[i], g_c3a[b * Cn + c], g_c3b[b * Cn + c]));
}

// ---------------- launch ----------------
extern "C" void kernel_launch(void* const* d_in, const int* in_sizes, int n_in,
                              void* d_out, int out_size) {
    const float* x      = (const float*)d_in[0];
    const float* w_exp  = (const float*)d_in[1];
    const float* gns    = (const float*)d_in[2];
    const float* gnb    = (const float*)d_in[3];
    const float* w1     = (const float*)d_in[4];
    const float* b1     = (const float*)d_in[5];
    const float* w2     = (const float*)d_in[6];
    const float* b2     = (const float*)d_in[7];
    const float* w_pw1  = (const float*)d_in[8];
    const float* gn1s   = (const float*)d_in[9];
    const float* gn1b   = (const float*)d_in[10];
    const float* w_dw   = (const float*)d_in[11];
    const float* gn2s   = (const float*)d_in[12];
    const float* gn2b   = (const float*)d_in[13];
    const float* w_pw2  = (const float*)d_in[14];
    const float* gn3s   = (const float*)d_in[15];
    const float* gn3b   = (const float*)d_in[16];
    float* out = (float*)d_out;

    k_zero<<<8, 256>>>();
    {
        dim3 g(32, 1, En * Bn);
        k_expert<<<g, 256>>>(x, w_exp);
    }
    k_router_fin<<<1, 256>>>(gns, gnb, w1, b1, w2, b2);
    k_combine<<<8192, 256>>>(x);
    {
        dim3 g(16, 8, Bn);
        k_pw1<<<g, 256>>>(w_pw1);
    }
    k_fin1<<<(Bn * HCn + 255) / 256, 256>>>(gn1s, gn1b);
    {
        dim3 g(4, HCn, Bn);
        k_dw<<<g, 256>>>(w_dw);
    }
    k_fin2<<<(Bn * HCn + 255) / 256, 256>>>(gn2s, gn2b);
    {
        dim3 g(8, 2, Bn);
        k_pw2<<<g, 256>>>(w_pw2);
    }
    k_fin3<<<(Bn * Cn + 255) / 256, 256>>>(gn3s, gn3b);
    k_out<<<8192, 256>>>(out);
}

// round 5
// speedup vs baseline: 2.1501x; 1.5702x over previous
#include <cuda_runtime.h>
#include <math.h>

#define En 8
#define Bn 16
#define Cn 128
#define Hn 64
#define Wn 64
#define HWn 4096
#define HCn 512
#define OHWn 1024

// ---------------- scratch (device globals; no allocation) ----------------
__device__ float g_y[(size_t)En * Bn * Cn * HWn];      // 268 MB expert conv raw
__device__ float g_comb[(size_t)Bn * Cn * HWn];        // 33.5 MB combined
__device__ float g_h1[(size_t)Bn * HCn * HWn];         // 134 MB pw1 raw
__device__ float g_h2[(size_t)Bn * HCn * HWn];         // 134 MB dw raw
__device__ float g_o[(size_t)Bn * Cn * OHWn];          // 8.4 MB pw2 raw
__device__ unsigned g_wt[(size_t)En * 16 * 9 * 8 * 128];  // W as tf32 bits, staging order
__device__ unsigned g_xt[(size_t)Bn * Cn * HWn];          // x as tf32 bits
__device__ float g_estats[En * Bn * 8 * 2];
__device__ float g_eca[En * Bn * Cn];
__device__ float g_ecb[En * Bn * Cn];
__device__ float g_wts[16][En];
__device__ float g_s1[Bn * 8 * 2];
__device__ float g_c1a[Bn * HCn];
__device__ float g_c1b[Bn * HCn];
__device__ float g_s2[Bn * 8 * 2];
__device__ float g_c2a[Bn * HCn];
__device__ float g_c2b[Bn * HCn];
__device__ float g_s3[Bn * 8 * 2];
__device__ float g_c3a[Bn * Cn];
__device__ float g_c3b[Bn * Cn];

__device__ __forceinline__ float silu_f(float v) { return v / (1.f + __expf(-v)); }

__device__ __forceinline__ unsigned to_tf32(float f) {
    unsigned r;
    asm("cvt.rna.tf32.f32 %0, %1;" : "=r"(r) : "f"(f));
    return r;
}

__device__ __forceinline__ void mma_tf32(float& c0, float& c1, float& c2, float& c3,
                                         unsigned a0, unsigned a1, unsigned a2, unsigned a3,
                                         unsigned b0, unsigned b1) {
    asm volatile(
        "mma.sync.aligned.m16n8k8.row.col.f32.tf32.tf32.f32 "
        "{%0,%1,%2,%3}, {%4,%5,%6,%7}, {%8,%9}, {%0,%1,%2,%3};"
        : "+f"(c0), "+f"(c1), "+f"(c2), "+f"(c3)
        : "r"(a0), "r"(a1), "r"(a2), "r"(a3), "r"(b0), "r"(b1));
}

// ---- packed f32x2 helpers ----
__device__ __forceinline__ unsigned long long pk2(float lo, float hi) {
    unsigned long long r;
    asm("mov.b64 %0, {%1, %2};" : "=l"(r) : "f"(lo), "f"(hi));
    return r;
}
__device__ __forceinline__ void ffma2(unsigned long long& d, unsigned long long a,
                                      unsigned long long b) {
    asm("fma.rn.f32x2 %0, %1, %2, %0;" : "+l"(d) : "l"(a), "l"(b));
}
__device__ __forceinline__ void unpk2(unsigned long long p, float& lo, float& hi) {
    asm("mov.b64 {%0, %1}, %2;" : "=f"(lo), "=f"(hi) : "l"(p));
}

// ---------------- K0: zero the stats accumulators ----------------
__global__ void k_zero() {
    int i = blockIdx.x * 256 + threadIdx.x;
    if (i < En * Bn * 8 * 2) g_estats[i] = 0.f;
    if (i < Bn * 8 * 2) { g_s1[i] = 0.f; g_s2[i] = 0.f; g_s3[i] = 0.f; }
}

// ---------------- W prep: [e][cc][tap][ci][co] tf32 bits ----------------
__global__ void k_wprep(const float* __restrict__ w_exp) {
    int i = blockIdx.x * 256 + threadIdx.x;
    if (i >= En * 16 * 9 * 8 * 128) return;
    int co = i & 127;
    int r = i >> 7;
    int ci = r & 7; r >>= 3;
    int tap = r % 9; r /= 9;
    int cc = r & 15;
    int e = r >> 4;
    g_wt[i] = to_tf32(w_exp[((size_t)(e * 128 + co) * 128 + cc * 8 + ci) * 9 + tap]);
}

// ---------------- X prep: tf32 bits, same NCHW layout ----------------
__global__ void k_xprep(const float* __restrict__ x) {
    int i = blockIdx.x * 256 + threadIdx.x;
    g_xt[i] = to_tf32(x[i]);
}

// ---------------- K1: expert 3x3 conv via tf32 mma.sync + GN stats ----------------
// block: one (e,b), 128 co, 2 image rows (128 px). 8 warps = 4 co-groups x 2 rows.
// warp: 32 co x 64 px (one image row).
__global__ __launch_bounds__(256, 2) void k_expert() {
    const int ty0 = blockIdx.x * 2;         // 32 tiles of 2 rows
    const int e = blockIdx.z >> 4;
    const int b = blockIdx.z & 15;

    __shared__ unsigned ws_s[9][8][136];    // [tap][ci][co pad136] 39168 B
    __shared__ unsigned xs_s[8][4][66];     // [ci][halo row][halo col] 8448 B

    const int tid = threadIdx.x;
    const int warp = tid >> 5;
    const int lane = tid & 31;
    const int wc = warp >> 1;               // co group (32 co)
    const int wp = warp & 1;                // image row within strip
    const int grp = lane >> 2;
    const int tig = lane & 3;

    float acc[2][8][4];
    #pragma unroll
    for (int mt = 0; mt < 2; mt++)
        #pragma unroll
        for (int nt = 0; nt < 8; nt++)
            #pragma unroll
            for (int q = 0; q < 4; q++) acc[mt][nt][q] = 0.f;

    const unsigned* wt = g_wt + (size_t)e * (16 * 9 * 8 * 128);
    const unsigned* xt = g_xt + (size_t)b * Cn * HWn;
    unsigned* wsf = &ws_s[0][0][0];

    for (int cc = 0; cc < 16; cc++) {
        // stage W: 9216 contiguous words -> padded smem, 9 uint4 copies/thread
        {
            const uint4* src = (const uint4*)(wt + cc * 9216);
            #pragma unroll
            for (int it = 0; it < 9; it++) {
                int idx = tid + it * 256;       // 0..2303
                int tc = idx >> 5, w4 = idx & 31;
                uint4 v = src[idx];
                *(uint4*)(wsf + tc * 136 + w4 * 4) = v;
            }
        }
        // stage X halo: 8 ci x 4 rows x 66 cols
        for (int idx = tid; idx < 2112; idx += 256) {
            int ci = idx / 264;
            int rem = idx - ci * 264;
            int row = rem / 66;
            int cx = rem - row * 66;
            int gy = ty0 - 1 + row, gx = cx - 1;
            unsigned v = 0u;
            if ((unsigned)gy < 64u && (unsigned)gx < 64u)
                v = xt[(size_t)(cc * 8 + ci) * HWn + gy * 64 + gx];
            xs_s[ci][row][cx] = v;
        }
        __syncthreads();

        #pragma unroll
        for (int tap = 0; tap < 9; tap++) {
            const int kh = tap / 3, kw = tap % 3;
            unsigned a0[2], a1[2], a2[2], a3[2];
            #pragma unroll
            for (int mt = 0; mt < 2; mt++) {
                int co_r = wc * 32 + mt * 16 + grp;
                a0[mt] = ws_s[tap][tig][co_r];
                a1[mt] = ws_s[tap][tig][co_r + 8];
                a2[mt] = ws_s[tap][tig + 4][co_r];
                a3[mt] = ws_s[tap][tig + 4][co_r + 8];
            }
            #pragma unroll
            for (int nt = 0; nt < 8; nt++) {
                int col = nt * 8 + grp + kw;
                unsigned b0 = xs_s[tig][wp + kh][col];
                unsigned b1 = xs_s[tig + 4][wp + kh][col];
                mma_tf32(acc[0][nt][0], acc[0][nt][1], acc[0][nt][2], acc[0][nt][3],
                         a0[0], a1[0], a2[0], a3[0], b0, b1);
                mma_tf32(acc[1][nt][0], acc[1][nt][1], acc[1][nt][2], acc[1][nt][3],
                         a0[1], a1[1], a2[1], a3[1], b0, b1);
            }
        }
        __syncthreads();
    }

    // epilogue: write y + per-warp GN group stats
    size_t ybase = (size_t)(e * Bn + b) * Cn * HWn;
    const int row = ty0 + wp;
    float ls[2] = {0.f, 0.f}, lq[2] = {0.f, 0.f};
    #pragma unroll
    for (int mt = 0; mt < 2; mt++) {
        int co = wc * 32 + mt * 16 + grp;
        #pragma unroll
        for (int nt = 0; nt < 8; nt++) {
            int colx = nt * 8 + 2 * tig;
            float2 v0 = make_float2(acc[mt][nt][0], acc[mt][nt][1]);
            float2 v1 = make_float2(acc[mt][nt][2], acc[mt][nt][3]);
            *(float2*)(g_y + ybase + (size_t)co * HWn + row * 64 + colx) = v0;
            *(float2*)(g_y + ybase + (size_t)(co + 8) * HWn + row * 64 + colx) = v1;
            ls[mt] += v0.x + v0.y + v1.x + v1.y;
            lq[mt] += v0.x * v0.x + v0.y * v0.y + v1.x * v1.x + v1.y * v1.y;
        }
    }
    #pragma unroll
    for (int mt = 0; mt < 2; mt++) {
        float s = ls[mt], q = lq[mt];
        #pragma unroll
        for (int off = 16; off > 0; off >>= 1) {
            s += __shfl_xor_sync(0xFFFFFFFFu, s, off);
            q += __shfl_xor_sync(0xFFFFFFFFu, q, off);
        }
        if (lane == 0) {
            int g = 2 * wc + mt;
            atomicAdd(&g_estats[((e * Bn + b) * 8 + g) * 2], s);
            atomicAdd(&g_estats[((e * Bn + b) * 8 + g) * 2 + 1], q);
        }
    }
}

// ---------------- K2: finalize expert GN coefs + router softmax ----------------
__global__ void k_router_fin(const float* __restrict__ gns, const float* __restrict__ gnb,
                             const float* __restrict__ w1, const float* __restrict__ b1,
                             const float* __restrict__ w2, const float* __restrict__ b2) {
    int tid = threadIdx.x;
    for (int i = tid; i < En * Bn * Cn; i += 256) {
        int e = i >> 11, b = (i >> 7) & 15, c = i & 127, g = c >> 4;
        float s = g_estats[((e * Bn + b) * 8 + g) * 2];
        float sq = g_estats[((e * Bn + b) * 8 + g) * 2 + 1];
        float mean = s * (1.f / 65536.f);
        float var = sq * (1.f / 65536.f) - mean * mean;
        float rstd = rsqrtf(var + 1e-5f);
        float a = rstd * gns[e * Cn + c];
        g_eca[i] = a;
        g_ecb[i] = gnb[e * Cn + c] - mean * a;
    }
    if (tid < 16) {
        int py = tid >> 2, px = tid & 3;
        float fe[32];
        float cy = (py + 0.5f) * 0.25f, cx = (px + 0.5f) * 0.25f;
        #pragma unroll
        for (int k = 0; k < 8; k++) {
            float fr = (float)(1 << k) * 3.14159265358979323846f;
            fe[k] = sinf(cy * fr);
            fe[8 + k] = cosf(cy * fr);
            fe[16 + k] = sinf(cx * fr);
            fe[24 + k] = cosf(cx * fr);
        }
        float hb[64];
        for (int j = 0; j < 64; j++) {
            float s = b1[j];
            for (int k = 0; k < 32; k++) s = fmaf(fe[k], w1[k * 64 + j], s);
            hb[j] = s / (1.f + expf(-s));
        }
        float lo[8];
        float mx = -1e30f;
        for (int ee = 0; ee < 8; ee++) {
            float s = b2[ee];
            for (int j = 0; j < 64; j++) s = fmaf(hb[j], w2[j * 8 + ee], s);
            lo[ee] = s;
            mx = fmaxf(mx, s);
        }
        float den = 0.f;
        for (int ee = 0; ee < 8; ee++) { lo[ee] = expf(lo[ee] - mx); den += lo[ee]; }
        float inv = 1.f / den;
        for (int ee = 0; ee < 8; ee++) g_wts[tid][ee] = lo[ee] * inv;
    }
}

// ---------------- K3: combine experts ----------------
__global__ void k_combine(const float* __restrict__ x) {
    size_t t = (size_t)blockIdx.x * 256 + threadIdx.x;
    size_t i = t * 4;
    int b = (int)(i >> 19);
    int c = (int)(i >> 12) & 127;
    int p = (int)(i & 4095);
    int patch = ((p >> 6) >> 4) * 4 + ((p & 63) >> 4);
    float4 outv = *(const float4*)(x + i);
    #pragma unroll
    for (int e = 0; e < 8; e++) {
        int ebc = (e * Bn + b) * Cn + c;
        float a = g_eca[ebc], bb = g_ecb[ebc];
        float wt = g_wts[patch][e];
        float4 y = *(const float4*)(g_y + (size_t)ebc * HWn + p);
        outv.x += wt * silu_f(fmaf(y.x, a, bb));
        outv.y += wt * silu_f(fmaf(y.y, a, bb));
        outv.z += wt * silu_f(fmaf(y.z, a, bb));
        outv.w += wt * silu_f(fmaf(y.w, a, bb));
    }
    *(float4*)(g_comb + i) = outv;
}

// ---------------- K4: pw1 1x1 conv (128->512) + gn1 stats (f32x2) ----------------
__global__ __launch_bounds__(256) void k_pw1(const float* __restrict__ w_pw1) {
    int pxb = blockIdx.x * 256;
    int hcb = blockIdx.y * 64;
    int b = blockIdx.z;
    __shared__ float As[16][64];
    __shared__ float Bs[16][256];
    __shared__ float sred[2];
    int tid = threadIdx.x;
    int pgg = tid & 31, cgg = tid >> 5;
    unsigned long long acc2[8][4];
    #pragma unroll
    for (int j = 0; j < 8; j++)
        #pragma unroll
        for (int op = 0; op < 4; op++) acc2[j][op] = 0ull;

    for (int kb = 0; kb < 128; kb += 16) {
        for (int idx = tid; idx < 1024; idx += 256) {
            int hc = idx >> 4, kk = idx & 15;
            As[kk][hc] = w_pw1[(size_t)(hcb + hc) * 128 + kb + kk];
        }
        for (int idx = tid; idx < 4096; idx += 256) {
            int kk = idx >> 8, ii = idx & 255;
            Bs[kk][ii] = g_comb[(size_t)(b * Cn + kb + kk) * HWn + pxb + ii];
        }
        __syncthreads();
        #pragma unroll
        for (int kk = 0; kk < 16; kk++) {
            float4 xa = *(const float4*)&Bs[kk][pgg * 8];
            float4 xb2 = *(const float4*)&Bs[kk][pgg * 8 + 4];
            float xvf[8] = {xa.x, xa.y, xa.z, xa.w, xb2.x, xb2.y, xb2.z, xb2.w};
            const unsigned long long* wp = (const unsigned long long*)&As[kk][cgg * 8];
            unsigned long long w0 = wp[0], w1 = wp[1], w2 = wp[2], w3 = wp[3];
            #pragma unroll
            for (int j = 0; j < 8; j++) {
                unsigned long long xvv = pk2(xvf[j], xvf[j]);
                ffma2(acc2[j][0], xvv, w0);
                ffma2(acc2[j][1], xvv, w1);
                ffma2(acc2[j][2], xvv, w2);
                ffma2(acc2[j][3], xvv, w3);
            }
        }
        __syncthreads();
    }
    float lsum = 0.f, lsq = 0.f;
    #pragma unroll
    for (int op = 0; op < 4; op++) {
        float vlo[8], vhi[8];
        #pragma unroll
        for (int j = 0; j < 8; j++) unpk2(acc2[j][op], vlo[j], vhi[j]);
        #pragma unroll
        for (int half = 0; half < 2; half++) {
            const float* v = half ? vhi : vlo;
            int hc = hcb + cgg * 8 + op * 2 + half;
            float* pp = g_h1 + (size_t)(b * HCn + hc) * HWn + pxb + pgg * 8;
            float4 v0 = make_float4(v[0], v[1], v[2], v[3]);
            float4 v1 = make_float4(v[4], v[5], v[6], v[7]);
            lsum += v0.x + v0.y + v0.z + v0.w + v1.x + v1.y + v1.z + v1.w;
            lsq += v0.x * v0.x + v0.y * v0.y + v0.z * v0.z + v0.w * v0.w +
                   v1.x * v1.x + v1.y * v1.y + v1.z * v1.z + v1.w * v1.w;
            *(float4*)pp = v0;
            *(float4*)(pp + 4) = v1;
        }
    }
    if (tid < 2) sred[tid] = 0.f;
    __syncthreads();
    atomicAdd(&sred[0], lsum);
    atomicAdd(&sred[1], lsq);
    __syncthreads();
    if (tid == 0) {
        int g = hcb >> 6;
        atomicAdd(&g_s1[(b * 8 + g) * 2], sred[0]);
        atomicAdd(&g_s1[(b * 8 + g) * 2 + 1], sred[1]);
    }
}

// ---------------- finalize kernels ----------------
__global__ void k_fin1(const float* __restrict__ s, const float* __restrict__ bias) {
    int i = blockIdx.x * 256 + threadIdx.x;
    if (i >= Bn * HCn) return;
    int b = i / HCn, c = i % HCn, g = c >> 6;
    float su = g_s1[(b * 8 + g) * 2], sq = g_s1[(b * 8 + g) * 2 + 1];
    float mean = su * (1.f / 262144.f);
    float var = sq * (1.f / 262144.f) - mean * mean;
    float rstd = rsqrtf(var + 1e-5f);
    float a = rstd * s[c];
    g_c1a[i] = a;
    g_c1b[i] = bias[c] - mean * a;
}
__global__ void k_fin2(const float* __restrict__ s, const float* __restrict__ bias) {
    int i = blockIdx.x * 256 + threadIdx.x;
    if (i >= Bn * HCn) return;
    int b = i / HCn, c = i % HCn, g = c >> 6;
    float su = g_s2[(b * 8 + g) * 2], sq = g_s2[(b * 8 + g) * 2 + 1];
    float mean = su * (1.f / 262144.f);
    float var = sq * (1.f / 262144.f) - mean * mean;
    float rstd = rsqrtf(var + 1e-5f);
    float a = rstd * s[c];
    g_c2a[i] = a;
    g_c2b[i] = bias[c] - mean * a;
}
__global__ void k_fin3(const float* __restrict__ s, const float* __restrict__ bias) {
    int i = blockIdx.x * 256 + threadIdx.x;
    if (i >= Bn * Cn) return;
    int b = i / Cn, c = i % Cn, g = c >> 4;
    float su = g_s3[(b * 8 + g) * 2], sq = g_s3[(b * 8 + g) * 2 + 1];
    float mean = su * (1.f / 16384.f);
    float var = sq * (1.f / 16384.f) - mean * mean;
    float rstd = rsqrtf(var + 1e-5f);
    float a = rstd * s[c];
    g_c3a[i] = a;
    g_c3b[i] = bias[c] - mean * a;
}

// ---------------- K5: depthwise 3x3 on silu(gn1(h1)) + gn2 stats ----------------
__global__ __launch_bounds__(256) void k_dw(const float* __restrict__ w_dw) {
    int rt = blockIdx.x;
    int hc = blockIdx.y;
    int b = blockIdx.z;
    __shared__ float xs[18][66];
    __shared__ float sred[2];
    int tid = threadIdx.x;
    float a = g_c1a[b * HCn + hc], bb = g_c1b[b * HCn + hc];
    const float* src = g_h1 + (size_t)(b * HCn + hc) * HWn;
    int r0 = rt * 16;
    for (int idx = tid; idx < 18 * 66; idx += 256) {
        int rr = idx / 66, cx = idx % 66;
        int gy = r0 - 1 + rr, gx = cx - 1;
        float v = 0.f;
        if ((unsigned)gy < 64u && (unsigned)gx < 64u)
            v = silu_f(fmaf(src[gy * 64 + gx], a, bb));
        xs[rr][cx] = v;
    }
    float wd[9];
    #pragma unroll
    for (int t9 = 0; t9 < 9; t9++) wd[t9] = __ldg(&w_dw[hc * 9 + t9]);
    __syncthreads();
    float lsum = 0.f, lsq = 0.f;
    float* dst = g_h2 + (size_t)(b * HCn + hc) * HWn;
    #pragma unroll
    for (int k4 = 0; k4 < 4; k4++) {
        int idx = tid + k4 * 256;
        int row = idx >> 6, col = idx & 63;
        float sum = 0.f;
        #pragma unroll
        for (int kh = 0; kh < 3; kh++)
            #pragma unroll
            for (int kw = 0; kw < 3; kw++)
                sum = fmaf(wd[kh * 3 + kw], xs[row + kh][col + kw], sum);
        dst[(r0 + row) * 64 + col] = sum;
        lsum += sum;
        lsq += sum * sum;
    }
    if (tid < 2) sred[tid] = 0.f;
    __syncthreads();
    atomicAdd(&sred[0], lsum);
    atomicAdd(&sred[1], lsq);
    __syncthreads();
    if (tid == 0) {
        int g = hc >> 6;
        atomicAdd(&g_s2[(b * 8 + g) * 2], sred[0]);
        atomicAdd(&g_s2[(b * 8 + g) * 2 + 1], sred[1]);
    }
}

// ---------------- K6: pw2 1x1 stride-2 (512->128) + gn3 stats ----------------
__global__ __launch_bounds__(256) void k_pw2(const float* __restrict__ w_pw2) {
    int pxb = blockIdx.x * 128;
    int cob = blockIdx.y * 64;
    int b = blockIdx.z;
    __shared__ float As[16][64];
    __shared__ float Bs[16][128];
    __shared__ float sred[8];
    int tid = threadIdx.x;
    int pg = tid & 15, cgp = tid >> 4;
    float acc[8][4];
    #pragma unroll
    for (int j = 0; j < 8; j++)
        #pragma unroll
        for (int o = 0; o < 4; o++) acc[j][o] = 0.f;

    for (int kb = 0; kb < 512; kb += 16) {
        for (int idx = tid; idx < 1024; idx += 256) {
            int co = idx >> 4, kk = idx & 15;
            As[kk][co] = w_pw2[(size_t)(cob + co) * 512 + kb + kk];
        }
        for (int idx = tid; idx < 2048; idx += 256) {
            int kk = idx >> 7, ii = idx & 127;
            int p = pxb + ii;
            int oh = p >> 5, ow = p & 31;
            int ch = kb + kk;
            float a = g_c2a[b * HCn + ch], bb = g_c2b[b * HCn + ch];
            float v = g_h2[(size_t)(b * HCn + ch) * HWn + oh * 128 + ow * 2];
            Bs[kk][ii] = silu_f(fmaf(v, a, bb));
        }
        __syncthreads();
        #pragma unroll
        for (int kk = 0; kk < 16; kk++) {
            float4 xa = *(const float4*)&Bs[kk][pg * 8];
            float4 xb2 = *(const float4*)&Bs[kk][pg * 8 + 4];
            float xv[8] = {xa.x, xa.y, xa.z, xa.w, xb2.x, xb2.y, xb2.z, xb2.w};
            float4 wa = *(const float4*)&As[kk][cgp * 4];
            float wv[4] = {wa.x, wa.y, wa.z, wa.w};
            #pragma unroll
            for (int j = 0; j < 8; j++)
                #pragma unroll
                for (int o = 0; o < 4; o++)
                    acc[j][o] = fmaf(xv[j], wv[o], acc[j][o]);
        }
        __syncthreads();
    }
    float lsum = 0.f, lsq = 0.f;
    #pragma unroll
    for (int o = 0; o < 4; o++) {
        int co = cob + cgp * 4 + o;
        float* dst = g_o + (size_t)(b * Cn + co) * OHWn + pxb + pg * 8;
        float4 v0 = make_float4(acc[0][o], acc[1][o], acc[2][o], acc[3][o]);
        float4 v1 = make_float4(acc[4][o], acc[5][o], acc[6][o], acc[7][o]);
        lsum += v0.x + v0.y + v0.z + v0.w + v1.x + v1.y + v1.z + v1.w;
        lsq += v0.x * v0.x + v0.y * v0.y + v0.z * v0.z + v0.w * v0.w +
               v1.x * v1.x + v1.y * v1.y + v1.z * v1.z + v1.w * v1.w;
        *(float4*)dst = v0;
        *(float4*)(dst + 4) = v1;
    }
    if (tid < 8) sred[tid] = 0.f;
    __syncthreads();
    atomicAdd(&sred[(cgp >> 2) * 2], lsum);
    atomicAdd(&sred[(cgp >> 2) * 2 + 1], lsq);
    __syncthreads();
    if (tid < 4) {
        int g = (cob >> 4) + tid;
        atomicAdd(&g_s3[(b * 8 + g) * 2], sred[tid * 2]);
        atomicAdd(&g_s3[(b * 8 + g) * 2 + 1], sred[tid * 2 + 1]);
    }
}

// ---------------- K7: final gn3 + silu ----------------
__global__ void k_out(float* __restrict__ out) {
    int i = blockIdx.x * 256 + threadIdx.x;
    int b = i >> 17;
    int c = (i >> 10) & 127;
    out[i] = silu_f(fmaf(g_o[i], g_c3a[b * Cn + c], g_c3b[b * Cn + c]));
}

// ---------------- launch ----------------
extern "C" void kernel_launch(void* const* d_in, const int* in_sizes, int n_in,
                              void* d_out, int out_size) {
    const float* x      = (const float*)d_in[0];
    const float* w_exp  = (const float*)d_in[1];
    const float* gns    = (const float*)d_in[2];
    const float* gnb    = (const float*)d_in[3];
    const float* w1     = (const float*)d_in[4];
    const float* b1     = (const float*)d_in[5];
    const float* w2     = (const float*)d_in[6];
    const float* b2     = (const float*)d_in[7];
    const float* w_pw1  = (const float*)d_in[8];
    const float* gn1s   = (const float*)d_in[9];
    const float* gn1b   = (const float*)d_in[10];
    const float* w_dw   = (const float*)d_in[11];
    const float* gn2s   = (const float*)d_in[12];
    const float* gn2b   = (const float*)d_in[13];
    const float* w_pw2  = (const float*)d_in[14];
    const float* gn3s   = (const float*)d_in[15];
    const float* gn3b   = (const float*)d_in[16];
    float* out = (float*)d_out;

    k_zero<<<8, 256>>>();
    k_wprep<<<(En * 16 * 9 * 8 * 128 + 255) / 256, 256>>>(w_exp);
    k_xprep<<<(Bn * Cn * HWn) / 256, 256>>>(x);
    {
        dim3 g(32, 1, En * Bn);
        k_expert<<<g, 256>>>();
    }
    k_router_fin<<<1, 256>>>(gns, gnb, w1, b1, w2, b2);
    k_combine<<<8192, 256>>>(x);
    {
        dim3 g(16, 8, Bn);
        k_pw1<<<g, 256>>>(w_pw1);
    }
    k_fin1<<<(Bn * HCn + 255) / 256, 256>>>(gn1s, gn1b);
    {
        dim3 g(4, HCn, Bn);
        k_dw<<<g, 256>>>(w_dw);
    }
    k_fin2<<<(Bn * HCn + 255) / 256, 256>>>(gn2s, gn2b);
    {
        dim3 g(8, 2, Bn);
        k_pw2<<<g, 256>>>(w_pw2);
    }
    k_fin3<<<(Bn * Cn + 255) / 256, 256>>>(gn3s, gn3b);
    k_out<<<8192, 256>>>(out);
}